// round 8
// baseline (speedup 1.0000x reference)
#include <cuda_runtime.h>
#include <math.h>
#include <stdint.h>

#define BB 4
#define TT 1024
#define DD 1024
#define HH 16
#define DKV 64
#define FFD 4096

// ---- packed split format: per element pair (2k, 2k+1):
//      word0 = [bf16hi(e0) | bf16hi(e1)], word1 = [bf16lo(e0) | bf16lo(e1)]
//      (4B/element, same as fp32; 16B group = one k-quad)

// ---------------- scratch (device globals; no allocation allowed) ----------------
__device__ float g_xy [2 * BB * TT * DD];            // packed y, x
__device__ float g_Wt [3 * DD * DD];                 // packed q/k/v weights (transposed)
__device__ float g_WoT[DD * DD];                     // packed Wo^T
__device__ float g_Win[FFD * DD];                    // packed W_in
__device__ float g_Wout[DD * FFD];                   // packed W_out
__device__ float g_QKV[3 * BB * TT * DD];            // packed Q,K,V
__device__ float g_Vt [BB * HH * DKV * TT];          // packed Vt (dinv folded)
__device__ float g_S  [(size_t)BB * HH * TT * TT];   // packed exp-scores (256 MB)
__device__ float g_dinv[BB * HH * TT];
__device__ float g_P  [BB * TT * DD];                // packed
__device__ float g_hid[(size_t)BB * TT * FFD];       // packed (64 MB)
__device__ float g_M  [BB * TT * DD];                // fp32
__device__ float g_o1 [BB * TT * DD];
__device__ float g_o2 [BB * TT * DD];
__device__ float g_ff [BB * TT * DD];

// ---------------- helpers ----------------
__device__ __forceinline__ uint32_t pack_bf16(float a, float b) {
    uint32_t d;
    asm("prmt.b32 %0, %1, %2, 0x7632;" : "=r"(d)
        : "r"(__float_as_uint(a)), "r"(__float_as_uint(b)));
    return d;
}
__device__ __forceinline__ float resid(float v) {
    return v - __uint_as_float(__float_as_uint(v) & 0xffff0000u);
}
__device__ __forceinline__ float bf_lo(uint32_t w) { return __uint_as_float(w << 16); }
__device__ __forceinline__ float bf_hi(uint32_t w) { return __uint_as_float(w & 0xffff0000u); }
__device__ __forceinline__ void mma_bf16(float* c, const uint32_t* a, const uint32_t* b) {
    asm volatile(
        "mma.sync.aligned.m16n8k16.row.col.f32.bf16.bf16.f32 "
        "{%0,%1,%2,%3}, {%4,%5,%6,%7}, {%8,%9}, {%0,%1,%2,%3};"
        : "+f"(c[0]), "+f"(c[1]), "+f"(c[2]), "+f"(c[3])
        : "r"(a[0]), "r"(a[1]), "r"(a[2]), "r"(a[3]), "r"(b[0]), "r"(b[1]));
}

// ---------------- bf16x3 mma GEMM on packed operands -------------------------------
// C[M,N] = alpha * A[M,K] @ B[N,K]^T ; A,B packed-split (addresses in fp32 elements).
// CTA: 128 x BN, 128 threads = 4 warps in a 2x2 grid, warp tile 64 x (BN/2).
// Inner loop: cp.async 16B groups -> LDS.128 -> HMMA. Crossbar bytes/MMA halved
// vs 8-warp 32x32 tiling (A and B each read by only 2 warps).
template<int BN, bool BIAS_, bool RELU_, bool EXP_, bool PACK_>
__global__ __launch_bounds__(128, (BN == 64) ? 3 : 2)
void mma_gemm(const float* __restrict__ A, const float* __restrict__ B,
              const float* __restrict__ bias, float* __restrict__ C,
              int K, int lda, int ldb, int ldc,
              long sA1, long sA2, long sB1, long sB2, long sC1, long sC2,
              int zdiv, float alpha, int gx, int gy, int ntiles)
{
    constexpr int BM = 128, BK = 32;
    constexpr int MT = 4;                   // 4 m16 tiles -> warp rows 64
    constexpr int NT = BN / 16;             // n8 tiles per warp (warp cols BN/2)
    constexpr int RSW = 48;                 // words per smem row (32 data + 16 pad)
    constexpr int STGW = (BM + BN) * RSW;
    constexpr int NLD = (BM + BN) * 8;      // 16B groups per stage

    extern __shared__ float sm[];
    uint32_t smb;
    asm("{ .reg .u64 t; cvta.to.shared.u64 t, %1; cvt.u32.u64 %0, t; }" : "=r"(smb) : "l"(sm));

    const int tid  = threadIdx.x;
    const int lane = tid & 31;
    const int wid  = tid >> 5;
    const int wm   = wid >> 1;              // 0..1
    const int wn   = wid & 1;               // 0..1
    const int g    = lane >> 2;
    const int tg   = lane & 3;

    const int ar = wm * 64 + g;
    const int br = wn * (BN / 2) + g;

    for (int tile = blockIdx.x; tile < ntiles; tile += gridDim.x) {
        const int z   = tile / (gx * gy);
        const int rem = tile % (gx * gy);
        const int row0 = (rem / gx) * BM;
        const int col0 = (rem % gx) * BN;
        const int z1 = z / zdiv, z2 = z % zdiv;
        const float* At = A + z1 * sA1 + z2 * sA2;
        const float* Bt = B + z1 * sB1 + z2 * sB2;
        float*       Ct = C + z1 * sC1 + z2 * sC2;

        float acc[MT][NT][4];
        #pragma unroll
        for (int i = 0; i < MT; i++)
            #pragma unroll
            for (int j = 0; j < NT; j++)
                #pragma unroll
                for (int q = 0; q < 4; q++) acc[i][j][q] = 0.f;

        const int nch = K / BK;

        auto copy_stage = [&](int s, int c) {
            const int kk = c * BK;
            #pragma unroll
            for (int i = tid; i < NLD; i += 128) {
                const bool isA = (i < BM * 8);
                const int j = isA ? i : (i - BM * 8);
                const int r = j >> 3, q = j & 7;
                const float* gp = isA ? (At + (long)(row0 + r) * lda + kk + q * 4)
                                      : (Bt + (long)(col0 + r) * ldb + kk + q * 4);
                uint32_t dst = smb + 4u * (uint32_t)(s * STGW + (isA ? 0 : BM * RSW) + r * RSW + q * 4);
                asm volatile("cp.async.cg.shared.global [%0], [%1], 16;" :: "r"(dst), "l"(gp));
            }
        };

        copy_stage(0, 0);
        asm volatile("cp.async.commit_group;" ::: "memory");

        for (int c = 0; c < nch; c++) {
            if (c + 1 < nch) copy_stage((c + 1) & 1, c + 1);
            asm volatile("cp.async.commit_group;" ::: "memory");
            asm volatile("cp.async.wait_group 1;" ::: "memory");
            __syncthreads();

            const float* Asm = sm + (c & 1) * STGW;
            const float* Bsm = Asm + BM * RSW;

            #pragma unroll
            for (int ks = 0; ks < 2; ks++) {
                const int qoff = (ks * 4 + tg) * 4;
                uint32_t Ah[MT][4], Al[MT][4];
                #pragma unroll
                for (int mt = 0; mt < MT; mt++) {
                    uint4 t0 = *(const uint4*)(Asm + (ar + mt * 16) * RSW + qoff);
                    uint4 t1 = *(const uint4*)(Asm + (ar + mt * 16 + 8) * RSW + qoff);
                    Ah[mt][0] = t0.x; Ah[mt][1] = t1.x; Ah[mt][2] = t0.z; Ah[mt][3] = t1.z;
                    Al[mt][0] = t0.y; Al[mt][1] = t1.y; Al[mt][2] = t0.w; Al[mt][3] = t1.w;
                }
                #pragma unroll
                for (int nt = 0; nt < NT; nt++) {
                    uint4 bv = *(const uint4*)(Bsm + (br + nt * 8) * RSW + qoff);
                    uint32_t Bh[2], Bl[2];
                    Bh[0] = bv.x; Bh[1] = bv.z;
                    Bl[0] = bv.y; Bl[1] = bv.w;
                    #pragma unroll
                    for (int mt = 0; mt < MT; mt++) mma_bf16(acc[mt][nt], Ah[mt], Bh);
                    #pragma unroll
                    for (int mt = 0; mt < MT; mt++) mma_bf16(acc[mt][nt], Ah[mt], Bl);
                    #pragma unroll
                    for (int mt = 0; mt < MT; mt++) mma_bf16(acc[mt][nt], Al[mt], Bh);
                }
            }
            __syncthreads();
        }

        // epilogue
        const int rbase = row0 + wm * 64 + g;
        const int cbase = col0 + wn * (BN / 2) + tg * 2;
        #pragma unroll
        for (int mt = 0; mt < MT; mt++) {
            #pragma unroll
            for (int half = 0; half < 2; half++) {
                const long gm = rbase + mt * 16 + half * 8;
                float* crow = Ct + gm * ldc;
                #pragma unroll
                for (int nt = 0; nt < NT; nt++) {
                    const int gn = cbase + nt * 8;
                    float v0 = acc[mt][nt][half * 2 + 0] * alpha;
                    float v1 = acc[mt][nt][half * 2 + 1] * alpha;
                    if (EXP_)  { v0 = __expf(v0); v1 = __expf(v1); }
                    if (BIAS_) { v0 += bias[gn]; v1 += bias[gn + 1]; }
                    if (RELU_) { v0 = fmaxf(v0, 0.f); v1 = fmaxf(v1, 0.f); }
                    if (PACK_) {
                        uint2 pk;
                        pk.x = pack_bf16(v0, v1);
                        pk.y = pack_bf16(resid(v0), resid(v1));
                        *(uint2*)(crow + gn) = pk;
                    } else {
                        float2 o; o.x = v0; o.y = v1;
                        *(float2*)(crow + gn) = o;
                    }
                }
            }
        }
    }
}

// -------- split pass: fp32 -> packed (pairs) ----------------------------------------
__global__ void split_pairs(const float* __restrict__ in, float* __restrict__ out, int npairs) {
    int i = blockIdx.x * 256 + threadIdx.x;
    if (i >= npairs) return;
    float2 v = *(const float2*)(in + 2 * i);
    uint2 pk;
    pk.x = pack_bf16(v.x, v.y);
    pk.y = pack_bf16(resid(v.x), resid(v.y));
    *(uint2*)(out + 2 * i) = pk;
}

// -------- transpose: out[z][c][r] = in[z][r][c] (*scale[z][r]), packed output -------
template<bool SC, bool PIN>
__global__ void transpose_pk(const float* __restrict__ in, float* __restrict__ out,
                             const float* __restrict__ scale,
                             int R, int ldin, int ldout,
                             long inS1, long inS2, int zdiv)
{
    __shared__ float tile[32][33];
    const int z = blockIdx.z;
    in  += (long)(z / zdiv) * inS1 + (long)(z % zdiv) * inS2;
    const long outz = (long)z * (long)gridDim.x * 32 * ldout;
    const int c0 = blockIdx.x * 32, r0 = blockIdx.y * 32;
    const int tx = threadIdx.x, ty = threadIdx.y;
    #pragma unroll
    for (int i = ty; i < 32; i += 8) {
        float v;
        if (PIN) {
            const uint32_t* ip = (const uint32_t*)(in + (long)(r0 + i) * ldin + ((c0 + tx) & ~1));
            uint32_t w0 = ip[0], w1 = ip[1];
            if ((tx & 1) == 0) v = bf_lo(w0) + bf_lo(w1);
            else               v = bf_hi(w0) + bf_hi(w1);
        } else {
            v = in[(long)(r0 + i) * ldin + c0 + tx];
        }
        if (SC) v *= scale[(long)z * R + r0 + i];
        tile[i][tx] = v;
    }
    __syncthreads();
    const int idx = ty * 32 + tx;
    const int p  = idx & 15;
    const int cr = idx >> 4;
    #pragma unroll
    for (int rr0 = 0; rr0 < 2; rr0++) {
        const int rr = cr + rr0 * 16;
        float v0 = tile[2 * p][rr];
        float v1 = tile[2 * p + 1][rr];
        uint2 pk;
        pk.x = pack_bf16(v0, v1);
        pk.y = pack_bf16(resid(v0), resid(v1));
        *(uint2*)(out + outz + (long)(c0 + rr) * ldout + r0 + 2 * p) = pk;
    }
}

// -------- deterministic per-column softmax denominator (packed S) -------------------
__global__ void colsum_inv(const float* __restrict__ S, float* __restrict__ dinv) {
    const int z = blockIdx.y;
    const int sp = blockIdx.x * 256 + threadIdx.x;
    const uint32_t* p = (const uint32_t*)(S + (long)z * 1048576 + 2 * sp);
    float a0 = 0.f, a1 = 0.f;
    #pragma unroll 4
    for (int t = 0; t < 1024; t++) {
        uint32_t w0 = p[(long)t * 1024];
        uint32_t w1 = p[(long)t * 1024 + 1];
        a0 += bf_lo(w0) + bf_lo(w1);
        a1 += bf_hi(w0) + bf_hi(w1);
    }
    dinv[z * 1024 + 2 * sp]     = 1.f / a0;
    dinv[z * 1024 + 2 * sp + 1] = 1.f / a1;
}

// ---------------- reductions + sub_norm ---------------------------------------------
__device__ __forceinline__ float blockReduceSum(float v) {
    __shared__ float sh[32];
    __syncthreads();
    int lane = threadIdx.x & 31, wid = threadIdx.x >> 5;
    #pragma unroll
    for (int o = 16; o; o >>= 1) v += __shfl_xor_sync(0xffffffffu, v, o);
    if (lane == 0) sh[wid] = v;
    __syncthreads();
    if (wid == 0) {
        v = (threadIdx.x < (blockDim.x >> 5)) ? sh[lane] : 0.f;
        #pragma unroll
        for (int o = 16; o; o >>= 1) v += __shfl_xor_sync(0xffffffffu, v, o);
        if (lane == 0) sh[0] = v;
    }
    __syncthreads();
    return sh[0];
}

__global__ void add_subnorm(const float* __restrict__ A, const float* __restrict__ R,
                            float* __restrict__ O) {
    long base = (long)blockIdx.x * 1024;
    int t = threadIdx.x;
    float v[4];
    float s = 0.f;
    #pragma unroll
    for (int j = 0; j < 4; j++) { v[j] = A[base + t + j * 256] + R[base + t + j * 256]; s += v[j]; }
    s = blockReduceSum(s);
    float mean = s * (1.f / 1024.f);
    float q = 0.f;
    #pragma unroll
    for (int j = 0; j < 4; j++) { float d = v[j] - mean; q += d * d; }
    q = blockReduceSum(q);
    float sd = sqrtf(q * (1.f / 1023.f));
    #pragma unroll
    for (int j = 0; j < 4; j++) O[base + t + j * 256] = v[j] - mean - sd;
}

// ---------------- host ----------------------------------------------------------------
static const int SMB128 = 2 * (128 + 128) * 48 * 4;  // 98,304 B -> 2 CTAs/SM
static const int SMB64  = 2 * (128 +  64) * 48 * 4;  // 73,728 B -> 3 CTAs/SM
static const int PG128  = 304;                        // 152 x 2
static const int PG64   = 456;                        // 152 x 3

extern "C" void kernel_launch(void* const* d_in, const int* in_sizes, int n_in,
                              void* d_out, int out_size) {
    const float* x    = (const float*)d_in[0];
    const float* y    = (const float*)d_in[1];
    const float* Wq1  = (const float*)d_in[2];
    const float* Wk1  = (const float*)d_in[3];
    const float* Wv1  = (const float*)d_in[4];
    const float* Wo1  = (const float*)d_in[5];
    const float* Wq2  = (const float*)d_in[6];
    const float* Wk2  = (const float*)d_in[7];
    const float* Wv2  = (const float*)d_in[8];
    const float* Wo2  = (const float*)d_in[9];
    const float* W_in = (const float*)d_in[10];
    const float* b_in = (const float*)d_in[11];
    const float* W_out= (const float*)d_in[12];
    const float* b_out= (const float*)d_in[13];
    float* out = (float*)d_out;

    float *xy, *Wt, *WoT, *Win, *Wout, *QKV, *Vt, *S, *dinv, *P, *hid, *M, *o1, *o2, *ff;
    cudaGetSymbolAddress((void**)&xy,  g_xy);
    cudaGetSymbolAddress((void**)&Wt,  g_Wt);
    cudaGetSymbolAddress((void**)&WoT, g_WoT);
    cudaGetSymbolAddress((void**)&Win, g_Win);
    cudaGetSymbolAddress((void**)&Wout,g_Wout);
    cudaGetSymbolAddress((void**)&QKV, g_QKV);
    cudaGetSymbolAddress((void**)&Vt,  g_Vt);
    cudaGetSymbolAddress((void**)&S,   g_S);
    cudaGetSymbolAddress((void**)&dinv,g_dinv);
    cudaGetSymbolAddress((void**)&P,   g_P);
    cudaGetSymbolAddress((void**)&hid, g_hid);
    cudaGetSymbolAddress((void**)&M,   g_M);
    cudaGetSymbolAddress((void**)&o1,  g_o1);
    cudaGetSymbolAddress((void**)&o2,  g_o2);
    cudaGetSymbolAddress((void**)&ff,  g_ff);

    cudaFuncSetAttribute(mma_gemm<128,false,false,false,true >, cudaFuncAttributeMaxDynamicSharedMemorySize, SMB128);
    cudaFuncSetAttribute(mma_gemm<128,false,false,true ,true >, cudaFuncAttributeMaxDynamicSharedMemorySize, SMB128);
    cudaFuncSetAttribute(mma_gemm<64 ,false,false,false,true >, cudaFuncAttributeMaxDynamicSharedMemorySize, SMB64);
    cudaFuncSetAttribute(mma_gemm<128,false,false,false,false>, cudaFuncAttributeMaxDynamicSharedMemorySize, SMB128);
    cudaFuncSetAttribute(mma_gemm<128,true ,true ,false,true >, cudaFuncAttributeMaxDynamicSharedMemorySize, SMB128);
    cudaFuncSetAttribute(mma_gemm<128,true ,false,false,false>, cudaFuncAttributeMaxDynamicSharedMemorySize, SMB128);

    const long Z0 = 0;
    const long XL = (long)BB * TT * DD;
    const long WL = (long)DD * DD;
    const long CL = (long)BB * TT * DD;
    dim3 blkT(32, 8);

    auto g128 = [&](int nt) { return dim3((unsigned)(nt < PG128 ? nt : PG128), 1, 1); };
    auto g64  = [&](int nt) { return dim3((unsigned)(nt < PG64  ? nt : PG64 ), 1, 1); };

    // ---- upfront splits: y -> xy[0], x -> xy[1], W_in, W_out
    split_pairs<<<(int)(XL/2 + 255)/256, 256>>>(y, xy, (int)(XL/2));
    split_pairs<<<(int)(XL/2 + 255)/256, 256>>>(x, xy + XL, (int)(XL/2));
    split_pairs<<<(int)(WL*4/2 + 255)/256, 256>>>(W_in,  Win,  (int)(WL*4/2));
    split_pairs<<<(int)(WL*4/2 + 255)/256, 256>>>(W_out, Wout, (int)(WL*4/2));

    auto run_mha = [&](long aS, const float* Wq, const float* Wk, const float* Wv,
                       const float* Wo, const float* resid_, float* obuf) {
        dim3 gw(2, 32, HH);
        transpose_pk<false,false><<<gw, blkT>>>(Wq, Wt,          nullptr, 1024, 64, 1024, 65536, 0, 1);
        transpose_pk<false,false><<<gw, blkT>>>(Wk, Wt + WL,     nullptr, 1024, 64, 1024, 65536, 0, 1);
        transpose_pk<false,false><<<gw, blkT>>>(Wv, Wt + 2 * WL, nullptr, 1024, 64, 1024, 65536, 0, 1);

        // merged QKV projections (z=0:Q, 1:K, 2:V), tiles 8x32x3 = 768
        mma_gemm<128,false,false,false,true><<<g128(768), 128, SMB128>>>(
            xy, Wt, nullptr, QKV, 1024, 1024, 1024, 1024,
            aS, aS, 2*WL, WL, 2*CL, CL, 2, 1.f, 8, 32, 768);

        // scores: S = exp(Q.K^T/8), tiles 8x8x64 = 4096
        mma_gemm<128,false,false,true,true><<<g128(4096), 128, SMB128>>>(
            QKV, QKV + CL, nullptr, S, 64, 1024, 1024, 1024,
            1048576, 64, 1048576, 64, 16777216, 1048576, HH, 0.125f, 8, 8, 4096);

        colsum_inv<<<dim3(2, BB * HH), 256>>>(S, dinv);

        dim3 gv(2, 32, BB * HH);
        transpose_pk<true,true><<<gv, blkT>>>(QKV + 2 * CL, Vt, dinv, 1024, 1024, 1024,
                                              1048576, 64, HH);

        // partial: P = S @ Vt^T, tiles 1x8x64 = 512 (BN=64)
        mma_gemm<64,false,false,false,true><<<g64(512), 128, SMB64>>>(
            S, Vt, nullptr, P, 1024, 1024, 1024, 1024,
            16777216, 1048576, 1048576, 65536, 1048576, 64, HH, 1.f, 1, 8, 512);

        // output projection, tiles 8x32 = 256 (fp32 out)
        dim3 gwo(32, 32, 1);
        transpose_pk<false,false><<<gwo, blkT>>>(Wo, WoT, nullptr, 1024, 1024, 1024, Z0, Z0, 1);
        mma_gemm<128,false,false,false,false><<<g128(256), 128, SMB128>>>(
            P, WoT, nullptr, M, 1024, 1024, 1024, 1024,
            Z0,Z0,Z0,Z0,Z0,Z0, 1, 1.f, 8, 32, 256);

        add_subnorm<<<BB * TT, 256>>>(M, resid_, obuf);
    };

    run_mha(0,  Wq1, Wk1, Wv1, Wo1, y, o1);
    run_mha(XL, Wq2, Wk2, Wv2, Wo2, o1, o2);

    // FFN: hid = relu(y @ W_in^T + b_in), tiles 32x32 = 1024 (packed out)
    mma_gemm<128,true,true,false,true><<<g128(1024), 128, SMB128>>>(
        xy, Win, b_in, hid, 1024, 1024, 1024, 4096,
        Z0,Z0,Z0,Z0,Z0,Z0, 1, 1.f, 32, 32, 1024);
    // ff = hid @ W_out^T + b_out, tiles 8x32 = 256 (fp32 out)
    mma_gemm<128,true,false,false,false><<<g128(256), 128, SMB128>>>(
        hid, Wout, b_out, ff, 4096, 4096, 4096, 1024,
        Z0,Z0,Z0,Z0,Z0,Z0, 1, 1.f, 8, 32, 256);

    add_subnorm<<<BB * TT, 256>>>(ff, o2, out);
}

// round 9
// speedup vs baseline: 1.5202x; 1.5202x over previous
#include <cuda_runtime.h>
#include <cuda_fp16.h>
#include <math.h>
#include <stdint.h>

#define BB 4
#define TT 1024
#define DD 1024
#define HH 16
#define DKV 64
#define FFD 4096

#define XL   (BB * TT * DD)            // 4,194,304
#define WL   (DD * DD)                 // 1,048,576
#define SL   ((long)BB * HH * TT * TT) // 67,108,864
#define HIDL ((long)BB * TT * FFD)     // 16,777,216

// ---- two-plane fp16 format: buffer = [hi: E halves][lo: E halves] ----------------
__device__ __align__(16) __half g_xy [2L * 2 * XL];   // y, x
__device__ __align__(16) __half g_Wt [2L * 3 * WL];   // q/k/v weights (transposed)
__device__ __align__(16) __half g_WoT[2L * WL];
__device__ __align__(16) __half g_Win[2L * 4 * WL];
__device__ __align__(16) __half g_Wout[2L * 4 * WL];
__device__ __align__(16) __half g_QKV[2L * 3 * XL];
__device__ __align__(16) __half g_Vt [2L * XL];
__device__ __align__(16) __half g_S  [2L * SL];       // 268 MB
__device__ __align__(16) __half g_P  [2L * XL];
__device__ __align__(16) __half g_hid[2L * HIDL];
__device__ float g_dinv[BB * HH * TT];
__device__ float g_M [XL];
__device__ float g_o1[XL];
__device__ float g_o2[XL];
__device__ float g_ff[XL];

// ---------------- helpers ----------------
__device__ __forceinline__ void mma_f16(float* c, const uint32_t* a, const uint32_t* b) {
    asm volatile(
        "mma.sync.aligned.m16n8k16.row.col.f32.f16.f16.f32 "
        "{%0,%1,%2,%3}, {%4,%5,%6,%7}, {%8,%9}, {%0,%1,%2,%3};"
        : "+f"(c[0]), "+f"(c[1]), "+f"(c[2]), "+f"(c[3])
        : "r"(a[0]), "r"(a[1]), "r"(a[2]), "r"(a[3]), "r"(b[0]), "r"(b[1]));
}

// ---------------- fp16x2 GEMM: C[M,N] = alpha * A[M,K] @ B[N,K]^T -------------------
// A two-plane (hi at A, lo at A+sApl): exact to 2^-22. B: hi plane only (2^-12 RN).
// 2 MMAs per k16 tile: Ah*Bh + Al*Bh. CTA 128x64, 8 warps (4x2), warp tile 32x32.
// smem/stage: A-hi 8K, A-lo 8K, B-hi 4K (row stride 64B, conflict-free, no pad).
// k within each 32-chunk permuted identically for A and B so per-thread fragments
// for both k16 steps are one LDS.128 per row.
template<bool BIAS_, bool RELU_, bool EXP_, bool PACK_>
__global__ __launch_bounds__(256, 3)
void mma_gemm(const __half* __restrict__ A, long sApl,
              const __half* __restrict__ B,
              const float* __restrict__ bias, void* __restrict__ Cv, long sCpl,
              int K, int lda, int ldb, int ldc,
              long sA1, long sA2, long sB1, long sB2, long sC1, long sC2,
              int zdiv, float alpha, int gx, int gy, int ntiles)
{
    constexpr int BM = 128, BN = 64, BK = 32;
    constexpr int MT = 2, NT = 4;
    constexpr int STGH = 10240;          // halves per stage (8K+8K+4K bytes)
    constexpr int OFF_AL = 4096;         // halves
    constexpr int OFF_B  = 8192;         // halves

    extern __shared__ __half smh[];
    uint32_t smb;
    asm("{ .reg .u64 t; cvta.to.shared.u64 t, %1; cvt.u32.u64 %0, t; }" : "=r"(smb) : "l"(smh));

    const int tid  = threadIdx.x;
    const int lane = tid & 31;
    const int wid  = tid >> 5;
    const int wm   = wid >> 1;           // 0..3
    const int wn   = wid & 1;            // 0..1
    const int g    = lane >> 2;
    const int tg   = lane & 3;

    const int ar = wm * 32 + g;
    const int br = wn * 32 + g;

    for (int tile = blockIdx.x; tile < ntiles; tile += gridDim.x) {
        const int z   = tile / (gx * gy);
        const int rem = tile % (gx * gy);
        const int row0 = (rem / gx) * BM;
        const int col0 = (rem % gx) * BN;
        const int z1 = z / zdiv, z2 = z % zdiv;
        const __half* Ahz = A + z1 * sA1 + z2 * sA2;
        const __half* Bhz = B + z1 * sB1 + z2 * sB2;

        float acc[MT][NT][4];
        #pragma unroll
        for (int i = 0; i < MT; i++)
            #pragma unroll
            for (int j = 0; j < NT; j++)
                #pragma unroll
                for (int q = 0; q < 4; q++) acc[i][j][q] = 0.f;

        const int nch = K / BK;

        // 1280 16B-groups per stage: A-hi 512, A-lo 512, B-hi 256 -> 5 per thread
        auto copy_stage = [&](int s, int c) {
            const int kk = c * BK;
            #pragma unroll
            for (int i = tid; i < 1280; i += 256) {
                const __half* src;
                uint32_t doff;
                if (i < 512) {
                    int r = i >> 2, q = i & 3;
                    src = Ahz + (long)(row0 + r) * lda + kk + q * 8;
                    doff = (uint32_t)(r * 32 + q * 8);
                } else if (i < 1024) {
                    int j = i - 512;
                    int r = j >> 2, q = j & 3;
                    src = Ahz + sApl + (long)(row0 + r) * lda + kk + q * 8;
                    doff = (uint32_t)(OFF_AL + r * 32 + q * 8);
                } else {
                    int j = i - 1024;
                    int r = j >> 2, q = j & 3;
                    src = Bhz + (long)(col0 + r) * ldb + kk + q * 8;
                    doff = (uint32_t)(OFF_B + r * 32 + q * 8);
                }
                uint32_t dst = smb + 2u * ((uint32_t)s * STGH + doff);
                asm volatile("cp.async.cg.shared.global [%0], [%1], 16;" :: "r"(dst), "l"(src));
            }
        };

        copy_stage(0, 0);
        asm volatile("cp.async.commit_group;" ::: "memory");

        for (int c = 0; c < nch; c++) {
            if (c + 1 < nch) copy_stage((c + 1) & 1, c + 1);
            asm volatile("cp.async.commit_group;" ::: "memory");
            asm volatile("cp.async.wait_group 1;" ::: "memory");
            __syncthreads();

            const __half* St = smh + (c & 1) * STGH;

            // B fragments: one LDS.128 per n-tile (covers both k16 steps)
            uint4 bq[NT];
            #pragma unroll
            for (int nt = 0; nt < NT; nt++)
                bq[nt] = *(const uint4*)(St + OFF_B + (br + 8 * nt) * 32 + tg * 8);

            #pragma unroll
            for (int mt = 0; mt < MT; mt++) {
                const __half* arow = St + (ar + 16 * mt) * 32 + tg * 8;
                uint4 h0 = *(const uint4*)(arow);
                uint4 h1 = *(const uint4*)(arow + 8 * 32);
                uint4 l0 = *(const uint4*)(arow + OFF_AL);
                uint4 l1 = *(const uint4*)(arow + OFF_AL + 8 * 32);
                uint32_t Ah0[4] = {h0.x, h1.x, h0.y, h1.y};
                uint32_t Al0[4] = {l0.x, l1.x, l0.y, l1.y};
                uint32_t Ah1[4] = {h0.z, h1.z, h0.w, h1.w};
                uint32_t Al1[4] = {l0.z, l1.z, l0.w, l1.w};
                #pragma unroll
                for (int nt = 0; nt < NT; nt++) {
                    uint32_t b0[2] = {bq[nt].x, bq[nt].y};
                    mma_f16(acc[mt][nt], Ah0, b0);
                    mma_f16(acc[mt][nt], Al0, b0);
                }
                #pragma unroll
                for (int nt = 0; nt < NT; nt++) {
                    uint32_t b1[2] = {bq[nt].z, bq[nt].w};
                    mma_f16(acc[mt][nt], Ah1, b1);
                    mma_f16(acc[mt][nt], Al1, b1);
                }
            }
            __syncthreads();
        }

        // epilogue
        float* Cf = (float*)Cv;
        __half* Ch = (__half*)Cv;
        const int rbase = row0 + wm * 32 + g;
        const int cbase = col0 + wn * 32 + tg * 2;
        #pragma unroll
        for (int mt = 0; mt < MT; mt++) {
            #pragma unroll
            for (int half_ = 0; half_ < 2; half_++) {
                const long gm = rbase + mt * 16 + half_ * 8;
                const long rowoff = z1 * sC1 + z2 * sC2 + gm * ldc;
                #pragma unroll
                for (int nt = 0; nt < NT; nt++) {
                    const int gn = cbase + nt * 8;
                    float v0 = acc[mt][nt][half_ * 2 + 0] * alpha;
                    float v1 = acc[mt][nt][half_ * 2 + 1] * alpha;
                    if (EXP_)  { v0 = __expf(v0); v1 = __expf(v1); }
                    if (BIAS_) { v0 += bias[gn]; v1 += bias[gn + 1]; }
                    if (RELU_) { v0 = fmaxf(v0, 0.f); v1 = fmaxf(v1, 0.f); }
                    if (PACK_) {
                        __half h0 = __float2half_rn(v0);
                        __half h1 = __float2half_rn(v1);
                        *(__half2*)(Ch + rowoff + gn) = __halves2half2(h0, h1);
                        __half e0 = __float2half_rn(v0 - __half2float(h0));
                        __half e1 = __float2half_rn(v1 - __half2float(h1));
                        *(__half2*)(Ch + sCpl + rowoff + gn) = __halves2half2(e0, e1);
                    } else {
                        float2 o; o.x = v0; o.y = v1;
                        *(float2*)(Cf + rowoff + gn) = o;
                    }
                }
            }
        }
    }
}

// -------- split pass: fp32 -> two fp16 planes ---------------------------------------
__global__ void split_pairs(const float* __restrict__ in, __half* __restrict__ out,
                            long pl, int npairs) {
    int i = blockIdx.x * 256 + threadIdx.x;
    if (i >= npairs) return;
    float2 v = *(const float2*)(in + 2 * i);
    __half h0 = __float2half_rn(v.x), h1 = __float2half_rn(v.y);
    *(__half2*)(out + 2 * i) = __halves2half2(h0, h1);
    __half e0 = __float2half_rn(v.x - __half2float(h0));
    __half e1 = __float2half_rn(v.y - __half2float(h1));
    *(__half2*)(out + pl + 2 * i) = __halves2half2(e0, e1);
}

// -------- transpose: out[z][c][r] = in[z][r][c] (*scale[z][r]); out = fp16 planes ---
// PIN: input is two fp16 planes (hi+lo reconstructed); else fp32.
template<bool SC, bool PIN>
__global__ void transpose_pk(const void* __restrict__ inv, __half* __restrict__ out,
                             long outPl, const float* __restrict__ scale,
                             int R, int ldin, int ldout,
                             long inS1, long inS2, long inPl, int zdiv)
{
    __shared__ float tile[32][33];
    const int z = blockIdx.z;
    const long inoff = (long)(z / zdiv) * inS1 + (long)(z % zdiv) * inS2;
    const long outz = (long)z * (long)gridDim.x * 32 * ldout;
    const int c0 = blockIdx.x * 32, r0 = blockIdx.y * 32;
    const int tx = threadIdx.x, ty = threadIdx.y;
    #pragma unroll
    for (int i = ty; i < 32; i += 8) {
        float v;
        long idx = (long)(r0 + i) * ldin + c0 + tx;
        if (PIN) {
            const __half* ih = (const __half*)inv + inoff;
            v = __half2float(ih[idx]) + __half2float(ih[inPl + idx]);
        } else {
            v = ((const float*)inv + inoff)[idx];
        }
        if (SC) v *= scale[(long)z * R + r0 + i];
        tile[i][tx] = v;
    }
    __syncthreads();
    #pragma unroll
    for (int i = ty; i < 32; i += 8) {
        float v = tile[tx][i];
        long o = outz + (long)(c0 + i) * ldout + r0 + tx;
        __half h = __float2half_rn(v);
        out[o] = h;
        out[outPl + o] = __float2half_rn(v - __half2float(h));
    }
}

// -------- deterministic per-column (query-axis) softmax denominator -----------------
__global__ void colsum_inv(const __half* __restrict__ S, long pl, float* __restrict__ dinv) {
    const int z = blockIdx.y;
    const int s = blockIdx.x * 256 + threadIdx.x;
    const __half* p = S + (long)z * 1048576 + s;
    float acc = 0.f;
    #pragma unroll 4
    for (int t = 0; t < 1024; t++)
        acc += __half2float(p[(long)t * 1024]) + __half2float(p[pl + (long)t * 1024]);
    dinv[z * 1024 + s] = 1.f / acc;
}

// ---------------- reductions + sub_norm ----------------------------------------------
__device__ __forceinline__ float blockReduceSum(float v) {
    __shared__ float sh[32];
    __syncthreads();
    int lane = threadIdx.x & 31, wid = threadIdx.x >> 5;
    #pragma unroll
    for (int o = 16; o; o >>= 1) v += __shfl_xor_sync(0xffffffffu, v, o);
    if (lane == 0) sh[wid] = v;
    __syncthreads();
    if (wid == 0) {
        v = (threadIdx.x < (blockDim.x >> 5)) ? sh[lane] : 0.f;
        #pragma unroll
        for (int o = 16; o; o >>= 1) v += __shfl_xor_sync(0xffffffffu, v, o);
        if (lane == 0) sh[0] = v;
    }
    __syncthreads();
    return sh[0];
}

__global__ void add_subnorm(const float* __restrict__ A, const float* __restrict__ R,
                            float* __restrict__ O) {
    long base = (long)blockIdx.x * 1024;
    int t = threadIdx.x;
    float v[4];
    float s = 0.f;
    #pragma unroll
    for (int j = 0; j < 4; j++) { v[j] = A[base + t + j * 256] + R[base + t + j * 256]; s += v[j]; }
    s = blockReduceSum(s);
    float mean = s * (1.f / 1024.f);
    float q = 0.f;
    #pragma unroll
    for (int j = 0; j < 4; j++) { float d = v[j] - mean; q += d * d; }
    q = blockReduceSum(q);
    float sd = sqrtf(q * (1.f / 1023.f));
    #pragma unroll
    for (int j = 0; j < 4; j++) O[base + t + j * 256] = v[j] - mean - sd;
}

// ---------------- host -----------------------------------------------------------------
static const int SMB   = 2 * 10240 * 2;   // 40,960 B
static const int PGRID = 456;             // 152 SMs x 3 CTAs

extern "C" void kernel_launch(void* const* d_in, const int* in_sizes, int n_in,
                              void* d_out, int out_size) {
    const float* x    = (const float*)d_in[0];
    const float* y    = (const float*)d_in[1];
    const float* Wq1  = (const float*)d_in[2];
    const float* Wk1  = (const float*)d_in[3];
    const float* Wv1  = (const float*)d_in[4];
    const float* Wo1  = (const float*)d_in[5];
    const float* Wq2  = (const float*)d_in[6];
    const float* Wk2  = (const float*)d_in[7];
    const float* Wv2  = (const float*)d_in[8];
    const float* Wo2  = (const float*)d_in[9];
    const float* W_in = (const float*)d_in[10];
    const float* b_in = (const float*)d_in[11];
    const float* W_out= (const float*)d_in[12];
    const float* b_out= (const float*)d_in[13];
    float* out = (float*)d_out;

    __half *xy, *Wt, *WoT, *Win, *Wout, *QKV, *Vt, *S, *P, *hid;
    float *dinv, *M, *o1, *o2, *ff;
    cudaGetSymbolAddress((void**)&xy,  g_xy);
    cudaGetSymbolAddress((void**)&Wt,  g_Wt);
    cudaGetSymbolAddress((void**)&WoT, g_WoT);
    cudaGetSymbolAddress((void**)&Win, g_Win);
    cudaGetSymbolAddress((void**)&Wout,g_Wout);
    cudaGetSymbolAddress((void**)&QKV, g_QKV);
    cudaGetSymbolAddress((void**)&Vt,  g_Vt);
    cudaGetSymbolAddress((void**)&S,   g_S);
    cudaGetSymbolAddress((void**)&P,   g_P);
    cudaGetSymbolAddress((void**)&hid, g_hid);
    cudaGetSymbolAddress((void**)&dinv,g_dinv);
    cudaGetSymbolAddress((void**)&M,   g_M);
    cudaGetSymbolAddress((void**)&o1,  g_o1);
    cudaGetSymbolAddress((void**)&o2,  g_o2);
    cudaGetSymbolAddress((void**)&ff,  g_ff);

    const long Z0 = 0;
    dim3 blkT(32, 8);
    auto gl = [&](int nt) { return dim3((unsigned)(nt < PGRID ? nt : PGRID), 1, 1); };

    // ---- upfront splits: y -> xy[0:XL], x -> xy[XL:2XL], W_in, W_out (plane = 2XL / 4WL)
    split_pairs<<<XL/2/256, 256>>>(y, xy,        2L*XL, XL/2);
    split_pairs<<<XL/2/256, 256>>>(x, xy + XL,   2L*XL, XL/2);
    split_pairs<<<4*WL/2/256, 256>>>(W_in,  Win,  4L*WL, 4*WL/2);
    split_pairs<<<4*WL/2/256, 256>>>(W_out, Wout, 4L*WL, 4*WL/2);

    auto run_mha = [&](long aS, const float* Wq, const float* Wk, const float* Wv,
                       const float* Wo, const float* resid_, float* obuf) {
        // per-head weights (H,D,dk) -> planes [(h,k), d]
        dim3 gw(2, 32, HH);
        transpose_pk<false,false><<<gw, blkT>>>(Wq, Wt,          3L*WL, nullptr, 1024, 64, 1024, 65536, 0, 0, 1);
        transpose_pk<false,false><<<gw, blkT>>>(Wk, Wt + WL,     3L*WL, nullptr, 1024, 64, 1024, 65536, 0, 0, 1);
        transpose_pk<false,false><<<gw, blkT>>>(Wv, Wt + 2 * WL, 3L*WL, nullptr, 1024, 64, 1024, 65536, 0, 0, 1);

        // merged QKV projections (z=0:Q,1:K,2:V), tiles 16x32x3 = 1536
        mma_gemm<false,false,false,true><<<gl(1536), 256, SMB>>>(
            xy, 2L*XL, Wt, nullptr, QKV, 3L*XL,
            1024, 1024, 1024, 1024,
            aS, aS, 2L*WL, WL, 2L*XL, XL, 2, 1.f, 16, 32, 1536);

        // scores: S = exp(Q.K^T/8), tiles 16x8x64 = 8192 (packed planes out)
        mma_gemm<false,false,true,true><<<gl(8192), 256, SMB>>>(
            QKV, 3L*XL, QKV + XL, nullptr, S, SL,
            64, 1024, 1024, 1024,
            1048576, 64, 1048576, 64, 16777216, 1048576, HH, 0.125f, 16, 8, 8192);

        colsum_inv<<<dim3(4, BB * HH), 256>>>(S, SL, dinv);

        // Vt planes: V (planes) -> *dinv -> [(b,h), v, s]
        dim3 gv(2, 32, BB * HH);
        transpose_pk<true,true><<<gv, blkT>>>(QKV + 2 * XL, Vt, (long)XL, dinv,
                                              1024, 1024, 1024, 1048576, 64, 3L*XL, HH);

        // partial: P = S @ Vt^T, tiles 1x8x64 = 512 (packed out)
        mma_gemm<false,false,false,true><<<gl(512), 256, SMB>>>(
            S, SL, Vt, nullptr, P, (long)XL,
            1024, 1024, 1024, 1024,
            16777216, 1048576, 1048576, 65536, 1048576, 64, HH, 1.f, 1, 8, 512);

        // output projection (fp32 out)
        dim3 gwo(32, 32, 1);
        transpose_pk<false,false><<<gwo, blkT>>>(Wo, WoT, (long)WL, nullptr, 1024, 1024, 1024, Z0, Z0, 0, 1);
        mma_gemm<false,false,false,false><<<gl(512), 256, SMB>>>(
            P, (long)XL, WoT, nullptr, M, Z0,
            1024, 1024, 1024, 1024,
            Z0,Z0,Z0,Z0,Z0,Z0, 1, 1.f, 16, 32, 512);

        add_subnorm<<<BB * TT, 256>>>(M, resid_, obuf);
    };

    run_mha(0,          Wq1, Wk1, Wv1, Wo1, y,  o1);
    run_mha((long)XL,   Wq2, Wk2, Wv2, Wo2, o1, o2);

    // FFN: hid = relu(y @ W_in^T + b_in), tiles 64x32 = 2048 (packed out)
    mma_gemm<true,true,false,true><<<gl(2048), 256, SMB>>>(
        xy, 2L*XL, Win, b_in, hid, HIDL,
        1024, 1024, 1024, 4096,
        Z0,Z0,Z0,Z0,Z0,Z0, 1, 1.f, 64, 32, 2048);
    // ff = hid @ W_out^T + b_out, tiles 16x32 = 512 (fp32 out)
    mma_gemm<true,false,false,false><<<gl(512), 256, SMB>>>(
        hid, HIDL, Wout, b_out, ff, Z0,
        4096, 4096, 4096, 1024,
        Z0,Z0,Z0,Z0,Z0,Z0, 1, 1.f, 16, 32, 512);

    add_subnorm<<<BB * TT, 256>>>(ff, o2, out);
}

// round 10
// speedup vs baseline: 2.5948x; 1.7068x over previous
#include <cuda_runtime.h>
#include <cuda_fp16.h>
#include <math.h>
#include <stdint.h>

#define BB 4
#define TT 1024
#define DD 1024
#define HH 16
#define DKV 64
#define FFD 4096

#define XL   (BB * TT * DD)            // 4,194,304
#define WL   (DD * DD)                 // 1,048,576
#define SL   ((long)BB * HH * TT * TT) // 67,108,864
#define HIDL ((long)BB * TT * FFD)     // 16,777,216

// ---- single-plane fp16 format (RN) -------------------------------------------------
__device__ __align__(16) __half g_xy [2 * XL];        // y, x
__device__ __align__(16) __half g_Wt [3 * WL];        // q/k/v weights (transposed)
__device__ __align__(16) __half g_WoT[WL];
__device__ __align__(16) __half g_Win[4 * WL];
__device__ __align__(16) __half g_Wout[4 * WL];
__device__ __align__(16) __half g_QKV[3 * XL];
__device__ __align__(16) __half g_Vt [XL];
__device__ __align__(16) __half g_S  [SL];            // 134 MB
__device__ __align__(16) __half g_P  [XL];
__device__ __align__(16) __half g_hid[HIDL];
__device__ float g_dinv[BB * HH * TT];
__device__ float g_M [XL];
__device__ float g_o1[XL];
__device__ float g_o2[XL];
__device__ float g_ff[XL];

// ---------------- helpers ----------------
__device__ __forceinline__ void mma_f16(float* c, const uint32_t* a, const uint32_t* b) {
    asm volatile(
        "mma.sync.aligned.m16n8k16.row.col.f32.f16.f16.f32 "
        "{%0,%1,%2,%3}, {%4,%5,%6,%7}, {%8,%9}, {%0,%1,%2,%3};"
        : "+f"(c[0]), "+f"(c[1]), "+f"(c[2]), "+f"(c[3])
        : "r"(a[0]), "r"(a[1]), "r"(a[2]), "r"(a[3]), "r"(b[0]), "r"(b[1]));
}

// ---------------- fp16 GEMM: C[M,N] = alpha * A[M,K] @ B[N,K]^T ---------------------
// A, B single-plane fp16 (RN). 1 MMA per k16 tile. CTA 128x64, 8 warps (4x2),
// warp tile 32x32, 2-stage cp.async, persistent CTAs. smem/stage 12 KB.
// k within each 32-chunk permuted identically for A and B so each thread's
// fragments for both k16 steps come from one LDS.128 per row.
template<bool BIAS_, bool RELU_, bool EXP_, bool PACK_>
__global__ __launch_bounds__(256, 3)
void mma_gemm(const __half* __restrict__ A, const __half* __restrict__ B,
              const float* __restrict__ bias, void* __restrict__ Cv,
              int K, int lda, int ldb, int ldc,
              long sA1, long sA2, long sB1, long sB2, long sC1, long sC2,
              int zdiv, float alpha, int gx, int gy, int ntiles)
{
    constexpr int BM = 128, BN = 64, BK = 32;
    constexpr int MT = 2, NT = 4;
    constexpr int STGH = 6144;           // halves per stage (A 4096 + B 2048)
    constexpr int OFF_B = 4096;          // halves

    extern __shared__ __half smh[];
    uint32_t smb;
    asm("{ .reg .u64 t; cvta.to.shared.u64 t, %1; cvt.u32.u64 %0, t; }" : "=r"(smb) : "l"(smh));

    const int tid  = threadIdx.x;
    const int lane = tid & 31;
    const int wid  = tid >> 5;
    const int wm   = wid >> 1;           // 0..3
    const int wn   = wid & 1;            // 0..1
    const int g    = lane >> 2;
    const int tg   = lane & 3;

    const int ar = wm * 32 + g;
    const int br = wn * 32 + g;

    for (int tile = blockIdx.x; tile < ntiles; tile += gridDim.x) {
        const int z   = tile / (gx * gy);
        const int rem = tile % (gx * gy);
        const int row0 = (rem / gx) * BM;
        const int col0 = (rem % gx) * BN;
        const int z1 = z / zdiv, z2 = z % zdiv;
        const __half* Ahz = A + z1 * sA1 + z2 * sA2;
        const __half* Bhz = B + z1 * sB1 + z2 * sB2;

        float acc[MT][NT][4];
        #pragma unroll
        for (int i = 0; i < MT; i++)
            #pragma unroll
            for (int j = 0; j < NT; j++)
                #pragma unroll
                for (int q = 0; q < 4; q++) acc[i][j][q] = 0.f;

        const int nch = K / BK;

        // 768 16B-groups per stage: A 512, B 256 -> 3 per thread
        auto copy_stage = [&](int s, int c) {
            const int kk = c * BK;
            #pragma unroll
            for (int i = tid; i < 768; i += 256) {
                const __half* src;
                uint32_t doff;
                if (i < 512) {
                    int r = i >> 2, q = i & 3;
                    src = Ahz + (long)(row0 + r) * lda + kk + q * 8;
                    doff = (uint32_t)(r * 32 + q * 8);
                } else {
                    int j = i - 512;
                    int r = j >> 2, q = j & 3;
                    src = Bhz + (long)(col0 + r) * ldb + kk + q * 8;
                    doff = (uint32_t)(OFF_B + r * 32 + q * 8);
                }
                uint32_t dst = smb + 2u * ((uint32_t)s * STGH + doff);
                asm volatile("cp.async.cg.shared.global [%0], [%1], 16;" :: "r"(dst), "l"(src));
            }
        };

        copy_stage(0, 0);
        asm volatile("cp.async.commit_group;" ::: "memory");

        for (int c = 0; c < nch; c++) {
            if (c + 1 < nch) copy_stage((c + 1) & 1, c + 1);
            asm volatile("cp.async.commit_group;" ::: "memory");
            asm volatile("cp.async.wait_group 1;" ::: "memory");
            __syncthreads();

            const __half* St = smh + (c & 1) * STGH;

            // B fragments: one LDS.128 per n-tile (covers both k16 steps)
            uint4 bq[NT];
            #pragma unroll
            for (int nt = 0; nt < NT; nt++)
                bq[nt] = *(const uint4*)(St + OFF_B + (br + 8 * nt) * 32 + tg * 8);

            #pragma unroll
            for (int mt = 0; mt < MT; mt++) {
                const __half* arow = St + (ar + 16 * mt) * 32 + tg * 8;
                uint4 h0 = *(const uint4*)(arow);
                uint4 h1 = *(const uint4*)(arow + 8 * 32);
                uint32_t Ah0[4] = {h0.x, h1.x, h0.y, h1.y};
                uint32_t Ah1[4] = {h0.z, h1.z, h0.w, h1.w};
                #pragma unroll
                for (int nt = 0; nt < NT; nt++) {
                    uint32_t b0[2] = {bq[nt].x, bq[nt].y};
                    mma_f16(acc[mt][nt], Ah0, b0);
                }
                #pragma unroll
                for (int nt = 0; nt < NT; nt++) {
                    uint32_t b1[2] = {bq[nt].z, bq[nt].w};
                    mma_f16(acc[mt][nt], Ah1, b1);
                }
            }
            __syncthreads();
        }

        // epilogue
        float* Cf = (float*)Cv;
        __half* Ch = (__half*)Cv;
        const int rbase = row0 + wm * 32 + g;
        const int cbase = col0 + wn * 32 + tg * 2;
        #pragma unroll
        for (int mt = 0; mt < MT; mt++) {
            #pragma unroll
            for (int half_ = 0; half_ < 2; half_++) {
                const long gm = rbase + mt * 16 + half_ * 8;
                const long rowoff = z1 * sC1 + z2 * sC2 + gm * ldc;
                #pragma unroll
                for (int nt = 0; nt < NT; nt++) {
                    const int gn = cbase + nt * 8;
                    float v0 = acc[mt][nt][half_ * 2 + 0] * alpha;
                    float v1 = acc[mt][nt][half_ * 2 + 1] * alpha;
                    if (EXP_)  { v0 = __expf(v0); v1 = __expf(v1); }
                    if (BIAS_) { v0 += bias[gn]; v1 += bias[gn + 1]; }
                    if (RELU_) { v0 = fmaxf(v0, 0.f); v1 = fmaxf(v1, 0.f); }
                    if (PACK_) {
                        *(__half2*)(Ch + rowoff + gn) =
                            __halves2half2(__float2half_rn(v0), __float2half_rn(v1));
                    } else {
                        float2 o; o.x = v0; o.y = v1;
                        *(float2*)(Cf + rowoff + gn) = o;
                    }
                }
            }
        }
    }
}

// -------- convert pass: fp32 -> fp16 (RN) --------------------------------------------
__global__ void split_pairs(const float* __restrict__ in, __half* __restrict__ out,
                            int npairs) {
    int i = blockIdx.x * 256 + threadIdx.x;
    if (i >= npairs) return;
    float2 v = *(const float2*)(in + 2 * i);
    *(__half2*)(out + 2 * i) = __halves2half2(__float2half_rn(v.x), __float2half_rn(v.y));
}

// -------- transpose: out[z][c][r] = in[z][r][c] (*scale[z][r]); fp16 out -------------
// PIN: input fp16; else fp32.
template<bool SC, bool PIN>
__global__ void transpose_pk(const void* __restrict__ inv, __half* __restrict__ out,
                             const float* __restrict__ scale,
                             int R, int ldin, int ldout,
                             long inS1, long inS2, int zdiv)
{
    __shared__ float tile[32][33];
    const int z = blockIdx.z;
    const long inoff = (long)(z / zdiv) * inS1 + (long)(z % zdiv) * inS2;
    const long outz = (long)z * (long)gridDim.x * 32 * ldout;
    const int c0 = blockIdx.x * 32, r0 = blockIdx.y * 32;
    const int tx = threadIdx.x, ty = threadIdx.y;
    #pragma unroll
    for (int i = ty; i < 32; i += 8) {
        float v;
        long idx = (long)(r0 + i) * ldin + c0 + tx;
        if (PIN) v = __half2float(((const __half*)inv + inoff)[idx]);
        else     v = ((const float*)inv + inoff)[idx];
        if (SC) v *= scale[(long)z * R + r0 + i];
        tile[i][tx] = v;
    }
    __syncthreads();
    #pragma unroll
    for (int i = ty; i < 32; i += 8) {
        long o = outz + (long)(c0 + i) * ldout + r0 + tx;
        out[o] = __float2half_rn(tile[tx][i]);
    }
}

// -------- deterministic per-column (query-axis) softmax denominator ------------------
__global__ void colsum_inv(const __half* __restrict__ S, float* __restrict__ dinv) {
    const int z = blockIdx.y;
    const int s = blockIdx.x * 256 + threadIdx.x;
    const __half* p = S + (long)z * 1048576 + s;
    float acc = 0.f;
    #pragma unroll 8
    for (int t = 0; t < 1024; t++) acc += __half2float(p[(long)t * 1024]);
    dinv[z * 1024 + s] = 1.f / acc;
}

// ---------------- reductions + sub_norm ----------------------------------------------
__device__ __forceinline__ float blockReduceSum(float v) {
    __shared__ float sh[32];
    __syncthreads();
    int lane = threadIdx.x & 31, wid = threadIdx.x >> 5;
    #pragma unroll
    for (int o = 16; o; o >>= 1) v += __shfl_xor_sync(0xffffffffu, v, o);
    if (lane == 0) sh[wid] = v;
    __syncthreads();
    if (wid == 0) {
        v = (threadIdx.x < (blockDim.x >> 5)) ? sh[lane] : 0.f;
        #pragma unroll
        for (int o = 16; o; o >>= 1) v += __shfl_xor_sync(0xffffffffu, v, o);
        if (lane == 0) sh[0] = v;
    }
    __syncthreads();
    return sh[0];
}

__global__ void add_subnorm(const float* __restrict__ A, const float* __restrict__ R,
                            float* __restrict__ O) {
    long base = (long)blockIdx.x * 1024;
    int t = threadIdx.x;
    float v[4];
    float s = 0.f;
    #pragma unroll
    for (int j = 0; j < 4; j++) { v[j] = A[base + t + j * 256] + R[base + t + j * 256]; s += v[j]; }
    s = blockReduceSum(s);
    float mean = s * (1.f / 1024.f);
    float q = 0.f;
    #pragma unroll
    for (int j = 0; j < 4; j++) { float d = v[j] - mean; q += d * d; }
    q = blockReduceSum(q);
    float sd = sqrtf(q * (1.f / 1023.f));
    #pragma unroll
    for (int j = 0; j < 4; j++) O[base + t + j * 256] = v[j] - mean - sd;
}

// ---------------- host -----------------------------------------------------------------
static const int SMB   = 2 * 6144 * 2;    // 24,576 B
static const int PGRID = 456;             // 152 SMs x 3 CTAs

extern "C" void kernel_launch(void* const* d_in, const int* in_sizes, int n_in,
                              void* d_out, int out_size) {
    const float* x    = (const float*)d_in[0];
    const float* y    = (const float*)d_in[1];
    const float* Wq1  = (const float*)d_in[2];
    const float* Wk1  = (const float*)d_in[3];
    const float* Wv1  = (const float*)d_in[4];
    const float* Wo1  = (const float*)d_in[5];
    const float* Wq2  = (const float*)d_in[6];
    const float* Wk2  = (const float*)d_in[7];
    const float* Wv2  = (const float*)d_in[8];
    const float* Wo2  = (const float*)d_in[9];
    const float* W_in = (const float*)d_in[10];
    const float* b_in = (const float*)d_in[11];
    const float* W_out= (const float*)d_in[12];
    const float* b_out= (const float*)d_in[13];
    float* out = (float*)d_out;

    __half *xy, *Wt, *WoT, *Win, *Wout, *QKV, *Vt, *S, *P, *hid;
    float *dinv, *M, *o1, *o2, *ff;
    cudaGetSymbolAddress((void**)&xy,  g_xy);
    cudaGetSymbolAddress((void**)&Wt,  g_Wt);
    cudaGetSymbolAddress((void**)&WoT, g_WoT);
    cudaGetSymbolAddress((void**)&Win, g_Win);
    cudaGetSymbolAddress((void**)&Wout,g_Wout);
    cudaGetSymbolAddress((void**)&QKV, g_QKV);
    cudaGetSymbolAddress((void**)&Vt,  g_Vt);
    cudaGetSymbolAddress((void**)&S,   g_S);
    cudaGetSymbolAddress((void**)&P,   g_P);
    cudaGetSymbolAddress((void**)&hid, g_hid);
    cudaGetSymbolAddress((void**)&dinv,g_dinv);
    cudaGetSymbolAddress((void**)&M,   g_M);
    cudaGetSymbolAddress((void**)&o1,  g_o1);
    cudaGetSymbolAddress((void**)&o2,  g_o2);
    cudaGetSymbolAddress((void**)&ff,  g_ff);

    const long Z0 = 0;
    dim3 blkT(32, 8);
    auto gl = [&](int nt) { return dim3((unsigned)(nt < PGRID ? nt : PGRID), 1, 1); };

    // ---- upfront converts: y -> xy[0:XL], x -> xy[XL:2XL], W_in, W_out
    split_pairs<<<XL/2/256, 256>>>(y, xy,      XL/2);
    split_pairs<<<XL/2/256, 256>>>(x, xy + XL, XL/2);
    split_pairs<<<4*WL/2/256, 256>>>(W_in,  Win,  4*WL/2);
    split_pairs<<<4*WL/2/256, 256>>>(W_out, Wout, 4*WL/2);

    auto run_mha = [&](long aS, const float* Wq, const float* Wk, const float* Wv,
                       const float* Wo, const float* resid_, float* obuf) {
        // per-head weights (H,D,dk) -> fp16 [(h,k), d]
        dim3 gw(2, 32, HH);
        transpose_pk<false,false><<<gw, blkT>>>(Wq, Wt,          nullptr, 1024, 64, 1024, 65536, 0, 1);
        transpose_pk<false,false><<<gw, blkT>>>(Wk, Wt + WL,     nullptr, 1024, 64, 1024, 65536, 0, 1);
        transpose_pk<false,false><<<gw, blkT>>>(Wv, Wt + 2 * WL, nullptr, 1024, 64, 1024, 65536, 0, 1);

        // merged QKV projections (z=0:Q,1:K,2:V), tiles 16x32x3 = 1536
        mma_gemm<false,false,false,true><<<gl(1536), 256, SMB>>>(
            xy, Wt, nullptr, QKV,
            1024, 1024, 1024, 1024,
            aS, aS, 2L*WL, WL, 2L*XL, XL, 2, 1.f, 16, 32, 1536);

        // scores: S = exp(Q.K^T/8), tiles 16x8x64 = 8192 (fp16 out)
        mma_gemm<false,false,true,true><<<gl(8192), 256, SMB>>>(
            QKV, QKV + XL, nullptr, S,
            64, 1024, 1024, 1024,
            1048576, 64, 1048576, 64, 16777216, 1048576, HH, 0.125f, 16, 8, 8192);

        colsum_inv<<<dim3(4, BB * HH), 256>>>(S, dinv);

        // Vt: V fp16 -> *dinv -> fp16 [(b,h), v, s]
        dim3 gv(2, 32, BB * HH);
        transpose_pk<true,true><<<gv, blkT>>>(QKV + 2 * XL, Vt, dinv,
                                              1024, 1024, 1024, 1048576, 64, HH);

        // partial: P = S @ Vt^T, tiles 1x8x64 = 512 (fp16 out)
        mma_gemm<false,false,false,true><<<gl(512), 256, SMB>>>(
            S, Vt, nullptr, P,
            1024, 1024, 1024, 1024,
            16777216, 1048576, 1048576, 65536, 1048576, 64, HH, 1.f, 1, 8, 512);

        // output projection (fp32 out)
        dim3 gwo(32, 32, 1);
        transpose_pk<false,false><<<gwo, blkT>>>(Wo, WoT, nullptr, 1024, 1024, 1024, Z0, Z0, 1);
        mma_gemm<false,false,false,false><<<gl(512), 256, SMB>>>(
            P, WoT, nullptr, M,
            1024, 1024, 1024, 1024,
            Z0,Z0,Z0,Z0,Z0,Z0, 1, 1.f, 16, 32, 512);

        add_subnorm<<<BB * TT, 256>>>(M, resid_, obuf);
    };

    run_mha(0,        Wq1, Wk1, Wv1, Wo1, y,  o1);
    run_mha((long)XL, Wq2, Wk2, Wv2, Wo2, o1, o2);

    // FFN: hid = relu(y @ W_in^T + b_in), tiles 64x32 = 2048 (fp16 out)
    mma_gemm<true,true,false,true><<<gl(2048), 256, SMB>>>(
        xy, Win, b_in, hid,
        1024, 1024, 1024, 4096,
        Z0,Z0,Z0,Z0,Z0,Z0, 1, 1.f, 64, 32, 2048);
    // ff = hid @ W_out^T + b_out, tiles 16x32 = 512 (fp32 out)
    mma_gemm<true,false,false,false><<<gl(512), 256, SMB>>>(
        hid, Wout, b_out, ff,
        4096, 4096, 4096, 1024,
        Z0,Z0,Z0,Z0,Z0,Z0, 1, 1.f, 16, 32, 512);

    add_subnorm<<<BB * TT, 256>>>(ff, o2, out);
}

// round 11
// speedup vs baseline: 3.0218x; 1.1645x over previous
#include <cuda_runtime.h>
#include <cuda_fp16.h>
#include <math.h>
#include <stdint.h>

#define BB 4
#define TT 1024
#define DD 1024
#define HH 16
#define DKV 64
#define FFD 4096

#define XL   (BB * TT * DD)            // 4,194,304
#define WL   (DD * DD)                 // 1,048,576
#define SL   ((long)BB * HH * TT * TT) // 67,108,864
#define HIDL ((long)BB * TT * FFD)     // 16,777,216

// ---- single-plane fp16 format (RN) -------------------------------------------------
__device__ __align__(16) __half g_xy [2 * XL];        // y, x
__device__ __align__(16) __half g_Wt [3 * WL];        // q/k/v weights (transposed)
__device__ __align__(16) __half g_WoT[WL];
__device__ __align__(16) __half g_Win[4 * WL];
__device__ __align__(16) __half g_Wout[4 * WL];
__device__ __align__(16) __half g_QKV[3 * XL];
__device__ __align__(16) __half g_Vt [XL];
__device__ __align__(16) __half g_S  [SL];            // 134 MB
__device__ __align__(16) __half g_P  [XL];
__device__ __align__(16) __half g_hid[HIDL];
__device__ float g_cpart[BB * HH * 8 * TT];           // per-tile-row column partials (2MB)
__device__ float g_dinv[BB * HH * TT];
__device__ float g_M [XL];
__device__ float g_o1[XL];
__device__ float g_o2[XL];
__device__ float g_ff[XL];

// ---------------- helpers ----------------
__device__ __forceinline__ void mma_f16(float* c, const uint32_t* a, const uint32_t* b) {
    asm volatile(
        "mma.sync.aligned.m16n8k16.row.col.f32.f16.f16.f32 "
        "{%0,%1,%2,%3}, {%4,%5,%6,%7}, {%8,%9}, {%0,%1,%2,%3};"
        : "+f"(c[0]), "+f"(c[1]), "+f"(c[2]), "+f"(c[3])
        : "r"(a[0]), "r"(a[1]), "r"(a[2]), "r"(a[3]), "r"(b[0]), "r"(b[1]));
}

// ---------------- fp16 GEMM: C[M,N] = alpha * A[M,K] @ B[N,K]^T ---------------------
// A, B single-plane fp16 (RN). 1 MMA per k16 tile. CTA 128x64, 8 warps (4x2),
// warp tile 32x32, 4-stage cp.async, persistent CTAs. smem/stage 12 KB.
// CSUM_: epilogue also emits deterministic per-tile column sums of the (exp'd)
// fp32 outputs into cpart[z][row0/128][col] (for query-axis softmax denominators).
template<bool BIAS_, bool RELU_, bool EXP_, bool PACK_, bool CSUM_>
__global__ __launch_bounds__(256, 3)
void mma_gemm(const __half* __restrict__ A, const __half* __restrict__ B,
              const float* __restrict__ bias, void* __restrict__ Cv,
              float* __restrict__ cpart,
              int K, int lda, int ldb, int ldc,
              long sA1, long sA2, long sB1, long sB2, long sC1, long sC2,
              int zdiv, float alpha, int gx, int gy, int ntiles)
{
    constexpr int BM = 128, BN = 64, BK = 32;
    constexpr int MT = 2, NT = 4;
    constexpr int NST = 4;
    constexpr int STGH = 6144;           // halves per stage (A 4096 + B 2048)
    constexpr int OFF_B = 4096;          // halves

    extern __shared__ __half smh[];
    uint32_t smb;
    asm("{ .reg .u64 t; cvta.to.shared.u64 t, %1; cvt.u32.u64 %0, t; }" : "=r"(smb) : "l"(smh));

    const int tid  = threadIdx.x;
    const int lane = tid & 31;
    const int wid  = tid >> 5;
    const int wm   = wid >> 1;           // 0..3
    const int wn   = wid & 1;            // 0..1
    const int g    = lane >> 2;
    const int tg   = lane & 3;

    const int ar = wm * 32 + g;
    const int br = wn * 32 + g;

    for (int tile = blockIdx.x; tile < ntiles; tile += gridDim.x) {
        const int z   = tile / (gx * gy);
        const int rem = tile % (gx * gy);
        const int trow = rem / gx;
        const int row0 = trow * BM;
        const int col0 = (rem % gx) * BN;
        const int z1 = z / zdiv, z2 = z % zdiv;
        const __half* Ahz = A + z1 * sA1 + z2 * sA2;
        const __half* Bhz = B + z1 * sB1 + z2 * sB2;

        float acc[MT][NT][4];
        #pragma unroll
        for (int i = 0; i < MT; i++)
            #pragma unroll
            for (int j = 0; j < NT; j++)
                #pragma unroll
                for (int q = 0; q < 4; q++) acc[i][j][q] = 0.f;

        const int nch = K / BK;

        // 768 16B-groups per stage: A 512, B 256 -> 3 per thread
        auto copy_stage = [&](int s, int c) {
            const int kk = c * BK;
            #pragma unroll
            for (int i = tid; i < 768; i += 256) {
                const __half* src;
                uint32_t doff;
                if (i < 512) {
                    int r = i >> 2, q = i & 3;
                    src = Ahz + (long)(row0 + r) * lda + kk + q * 8;
                    doff = (uint32_t)(r * 32 + q * 8);
                } else {
                    int j = i - 512;
                    int r = j >> 2, q = j & 3;
                    src = Bhz + (long)(col0 + r) * ldb + kk + q * 8;
                    doff = (uint32_t)(OFF_B + r * 32 + q * 8);
                }
                uint32_t dst = smb + 2u * ((uint32_t)s * STGH + doff);
                asm volatile("cp.async.cg.shared.global [%0], [%1], 16;" :: "r"(dst), "l"(src));
            }
        };

        // prologue: stages 0..2
        #pragma unroll
        for (int s = 0; s < NST - 1; s++) {
            if (s < nch) copy_stage(s, s);
            asm volatile("cp.async.commit_group;" ::: "memory");
        }

        for (int c = 0; c < nch; c++) {
            if (c + NST - 1 < nch) copy_stage((c + NST - 1) & (NST - 1), c + NST - 1);
            asm volatile("cp.async.commit_group;" ::: "memory");
            asm volatile("cp.async.wait_group %0;" :: "n"(NST - 1) : "memory");
            __syncthreads();

            const __half* St = smh + (c & (NST - 1)) * STGH;

            uint4 bq[NT];
            #pragma unroll
            for (int nt = 0; nt < NT; nt++)
                bq[nt] = *(const uint4*)(St + OFF_B + (br + 8 * nt) * 32 + tg * 8);

            #pragma unroll
            for (int mt = 0; mt < MT; mt++) {
                const __half* arow = St + (ar + 16 * mt) * 32 + tg * 8;
                uint4 h0 = *(const uint4*)(arow);
                uint4 h1 = *(const uint4*)(arow + 8 * 32);
                uint32_t Ah0[4] = {h0.x, h1.x, h0.y, h1.y};
                uint32_t Ah1[4] = {h0.z, h1.z, h0.w, h1.w};
                #pragma unroll
                for (int nt = 0; nt < NT; nt++) {
                    uint32_t b0[2] = {bq[nt].x, bq[nt].y};
                    mma_f16(acc[mt][nt], Ah0, b0);
                }
                #pragma unroll
                for (int nt = 0; nt < NT; nt++) {
                    uint32_t b1[2] = {bq[nt].z, bq[nt].w};
                    mma_f16(acc[mt][nt], Ah1, b1);
                }
            }
            __syncthreads();
        }

        // epilogue
        float* Cf = (float*)Cv;
        __half* Ch = (__half*)Cv;
        float cs[NT][2];
        if (CSUM_) {
            #pragma unroll
            for (int nt = 0; nt < NT; nt++) { cs[nt][0] = 0.f; cs[nt][1] = 0.f; }
        }
        const int rbase = row0 + wm * 32 + g;
        const int cbase = col0 + wn * 32 + tg * 2;
        #pragma unroll
        for (int mt = 0; mt < MT; mt++) {
            #pragma unroll
            for (int half_ = 0; half_ < 2; half_++) {
                const long gm = rbase + mt * 16 + half_ * 8;
                const long rowoff = z1 * sC1 + z2 * sC2 + gm * ldc;
                #pragma unroll
                for (int nt = 0; nt < NT; nt++) {
                    const int gn = cbase + nt * 8;
                    float v0 = acc[mt][nt][half_ * 2 + 0] * alpha;
                    float v1 = acc[mt][nt][half_ * 2 + 1] * alpha;
                    if (EXP_)  { v0 = __expf(v0); v1 = __expf(v1); }
                    if (BIAS_) { v0 += bias[gn]; v1 += bias[gn + 1]; }
                    if (RELU_) { v0 = fmaxf(v0, 0.f); v1 = fmaxf(v1, 0.f); }
                    if (CSUM_) { cs[nt][0] += v0; cs[nt][1] += v1; }
                    if (PACK_) {
                        *(__half2*)(Ch + rowoff + gn) =
                            __halves2half2(__float2half_rn(v0), __float2half_rn(v1));
                    } else {
                        float2 o; o.x = v0; o.y = v1;
                        *(float2*)(Cf + rowoff + gn) = o;
                    }
                }
            }
        }

        if (CSUM_) {
            // reduce cs over g (lanes differing in bits 2..4) -> 32-row column sums
            #pragma unroll
            for (int nt = 0; nt < NT; nt++) {
                #pragma unroll
                for (int p = 0; p < 2; p++) {
                    float v = cs[nt][p];
                    v += __shfl_xor_sync(0xffffffffu, v, 4);
                    v += __shfl_xor_sync(0xffffffffu, v, 8);
                    v += __shfl_xor_sync(0xffffffffu, v, 16);
                    cs[nt][p] = v;
                }
            }
            float* colpart = (float*)smh;   // 4 x 64 floats (stage buffers are dead)
            if (g == 0) {
                #pragma unroll
                for (int nt = 0; nt < NT; nt++) {
                    int lc = wn * 32 + tg * 2 + nt * 8;
                    colpart[wm * 64 + lc]     = cs[nt][0];
                    colpart[wm * 64 + lc + 1] = cs[nt][1];
                }
            }
            __syncthreads();
            if (tid < 64) {
                float s4 = colpart[tid] + colpart[64 + tid] +
                           colpart[128 + tid] + colpart[192 + tid];
                cpart[(long)z * 8192 + trow * 1024 + col0 + tid] = s4;
            }
            __syncthreads();   // protect colpart before next tile's cp.async
        }
    }
}

// -------- convert pass: fp32 -> fp16 (RN) --------------------------------------------
__global__ void split_pairs(const float* __restrict__ in, __half* __restrict__ out,
                            int npairs) {
    int i = blockIdx.x * 256 + threadIdx.x;
    if (i >= npairs) return;
    float2 v = *(const float2*)(in + 2 * i);
    *(__half2*)(out + 2 * i) = __halves2half2(__float2half_rn(v.x), __float2half_rn(v.y));
}

// -------- dinv from column partials: dinv[z][s] = 1/sum_tr cpart[z][tr][s] -----------
__global__ void inv_partials(const float* __restrict__ cpart, float* __restrict__ dinv) {
    int i = blockIdx.x * 256 + threadIdx.x;     // 65536 total
    int z = i >> 10, s = i & 1023;
    const float* p = cpart + (long)z * 8192 + s;
    float a = 0.f;
    #pragma unroll
    for (int tr = 0; tr < 8; tr++) a += p[tr * 1024];
    dinv[i] = 1.f / a;
}

// -------- transpose: out[z][c][r] = in[z][r][c] (*scale[z][r]); fp16 out -------------
template<bool SC, bool PIN>
__global__ void transpose_pk(const void* __restrict__ inv, __half* __restrict__ out,
                             const float* __restrict__ scale,
                             int R, int ldin, int ldout,
                             long inS1, long inS2, int zdiv)
{
    __shared__ float tile[32][33];
    const int z = blockIdx.z;
    const long inoff = (long)(z / zdiv) * inS1 + (long)(z % zdiv) * inS2;
    const long outz = (long)z * (long)gridDim.x * 32 * ldout;
    const int c0 = blockIdx.x * 32, r0 = blockIdx.y * 32;
    const int tx = threadIdx.x, ty = threadIdx.y;
    #pragma unroll
    for (int i = ty; i < 32; i += 8) {
        float v;
        long idx = (long)(r0 + i) * ldin + c0 + tx;
        if (PIN) v = __half2float(((const __half*)inv + inoff)[idx]);
        else     v = ((const float*)inv + inoff)[idx];
        if (SC) v *= scale[(long)z * R + r0 + i];
        tile[i][tx] = v;
    }
    __syncthreads();
    #pragma unroll
    for (int i = ty; i < 32; i += 8) {
        long o = outz + (long)(c0 + i) * ldout + r0 + tx;
        out[o] = __float2half_rn(tile[tx][i]);
    }
}

// ---------------- reductions + sub_norm ----------------------------------------------
__device__ __forceinline__ float blockReduceSum(float v) {
    __shared__ float sh[32];
    __syncthreads();
    int lane = threadIdx.x & 31, wid = threadIdx.x >> 5;
    #pragma unroll
    for (int o = 16; o; o >>= 1) v += __shfl_xor_sync(0xffffffffu, v, o);
    if (lane == 0) sh[wid] = v;
    __syncthreads();
    if (wid == 0) {
        v = (threadIdx.x < (blockDim.x >> 5)) ? sh[lane] : 0.f;
        #pragma unroll
        for (int o = 16; o; o >>= 1) v += __shfl_xor_sync(0xffffffffu, v, o);
        if (lane == 0) sh[0] = v;
    }
    __syncthreads();
    return sh[0];
}

__global__ void add_subnorm(const float* __restrict__ A, const float* __restrict__ R,
                            float* __restrict__ O) {
    long base = (long)blockIdx.x * 1024;
    int t = threadIdx.x;
    float v[4];
    float s = 0.f;
    #pragma unroll
    for (int j = 0; j < 4; j++) { v[j] = A[base + t + j * 256] + R[base + t + j * 256]; s += v[j]; }
    s = blockReduceSum(s);
    float mean = s * (1.f / 1024.f);
    float q = 0.f;
    #pragma unroll
    for (int j = 0; j < 4; j++) { float d = v[j] - mean; q += d * d; }
    q = blockReduceSum(q);
    float sd = sqrtf(q * (1.f / 1023.f));
    #pragma unroll
    for (int j = 0; j < 4; j++) O[base + t + j * 256] = v[j] - mean - sd;
}

// ---------------- host -----------------------------------------------------------------
static const int SMB   = 4 * 6144 * 2;    // 49,152 B -> 3 CTAs/SM (147 KB)
static const int PGRID = 456;             // 152 SMs x 3 CTAs

extern "C" void kernel_launch(void* const* d_in, const int* in_sizes, int n_in,
                              void* d_out, int out_size) {
    const float* x    = (const float*)d_in[0];
    const float* y    = (const float*)d_in[1];
    const float* Wq1  = (const float*)d_in[2];
    const float* Wk1  = (const float*)d_in[3];
    const float* Wv1  = (const float*)d_in[4];
    const float* Wo1  = (const float*)d_in[5];
    const float* Wq2  = (const float*)d_in[6];
    const float* Wk2  = (const float*)d_in[7];
    const float* Wv2  = (const float*)d_in[8];
    const float* Wo2  = (const float*)d_in[9];
    const float* W_in = (const float*)d_in[10];
    const float* b_in = (const float*)d_in[11];
    const float* W_out= (const float*)d_in[12];
    const float* b_out= (const float*)d_in[13];
    float* out = (float*)d_out;

    __half *xy, *Wt, *WoT, *Win, *Wout, *QKV, *Vt, *S, *P, *hid;
    float *cpart, *dinv, *M, *o1, *o2, *ff;
    cudaGetSymbolAddress((void**)&xy,  g_xy);
    cudaGetSymbolAddress((void**)&Wt,  g_Wt);
    cudaGetSymbolAddress((void**)&WoT, g_WoT);
    cudaGetSymbolAddress((void**)&Win, g_Win);
    cudaGetSymbolAddress((void**)&Wout,g_Wout);
    cudaGetSymbolAddress((void**)&QKV, g_QKV);
    cudaGetSymbolAddress((void**)&Vt,  g_Vt);
    cudaGetSymbolAddress((void**)&S,   g_S);
    cudaGetSymbolAddress((void**)&P,   g_P);
    cudaGetSymbolAddress((void**)&hid, g_hid);
    cudaGetSymbolAddress((void**)&cpart, g_cpart);
    cudaGetSymbolAddress((void**)&dinv,g_dinv);
    cudaGetSymbolAddress((void**)&M,   g_M);
    cudaGetSymbolAddress((void**)&o1,  g_o1);
    cudaGetSymbolAddress((void**)&o2,  g_o2);
    cudaGetSymbolAddress((void**)&ff,  g_ff);

    cudaFuncSetAttribute(mma_gemm<false,false,false,true ,false>, cudaFuncAttributeMaxDynamicSharedMemorySize, SMB);
    cudaFuncSetAttribute(mma_gemm<false,false,true ,true ,true >, cudaFuncAttributeMaxDynamicSharedMemorySize, SMB);
    cudaFuncSetAttribute(mma_gemm<false,false,false,false,false>, cudaFuncAttributeMaxDynamicSharedMemorySize, SMB);
    cudaFuncSetAttribute(mma_gemm<true ,true ,false,true ,false>, cudaFuncAttributeMaxDynamicSharedMemorySize, SMB);
    cudaFuncSetAttribute(mma_gemm<true ,false,false,false,false>, cudaFuncAttributeMaxDynamicSharedMemorySize, SMB);

    const long Z0 = 0;
    dim3 blkT(32, 8);
    auto gl = [&](int nt) { return dim3((unsigned)(nt < PGRID ? nt : PGRID), 1, 1); };

    // ---- upfront converts
    split_pairs<<<XL/2/256, 256>>>(y, xy,      XL/2);
    split_pairs<<<XL/2/256, 256>>>(x, xy + XL, XL/2);
    split_pairs<<<4*WL/2/256, 256>>>(W_in,  Win,  4*WL/2);
    split_pairs<<<4*WL/2/256, 256>>>(W_out, Wout, 4*WL/2);

    auto run_mha = [&](long aS, const float* Wq, const float* Wk, const float* Wv,
                       const float* Wo, const float* resid_, float* obuf) {
        // per-head weights (H,D,dk) -> fp16 [(h,k), d]
        dim3 gw(2, 32, HH);
        transpose_pk<false,false><<<gw, blkT>>>(Wq, Wt,          nullptr, 1024, 64, 1024, 65536, 0, 1);
        transpose_pk<false,false><<<gw, blkT>>>(Wk, Wt + WL,     nullptr, 1024, 64, 1024, 65536, 0, 1);
        transpose_pk<false,false><<<gw, blkT>>>(Wv, Wt + 2 * WL, nullptr, 1024, 64, 1024, 65536, 0, 1);

        // merged QKV projections (z=0:Q,1:K,2:V), tiles 16x32x3 = 1536
        mma_gemm<false,false,false,true,false><<<gl(1536), 256, SMB>>>(
            xy, Wt, nullptr, QKV, nullptr,
            1024, 1024, 1024, 1024,
            aS, aS, 2L*WL, WL, 2L*XL, XL, 2, 1.f, 16, 32, 1536);

        // scores: S = exp(Q.K^T/8), tiles 16x8x64 = 8192 (fp16 out + column partials)
        mma_gemm<false,false,true,true,true><<<gl(8192), 256, SMB>>>(
            QKV, QKV + XL, nullptr, S, cpart,
            64, 1024, 1024, 1024,
            1048576, 64, 1048576, 64, 16777216, 1048576, HH, 0.125f, 16, 8, 8192);

        // dinv from 2MB partials (deterministic)
        inv_partials<<<256, 256>>>(cpart, dinv);

        // Vt: V fp16 -> *dinv -> fp16 [(b,h), v, s]
        dim3 gv(2, 32, BB * HH);
        transpose_pk<true,true><<<gv, blkT>>>(QKV + 2 * XL, Vt, dinv,
                                              1024, 1024, 1024, 1048576, 64, HH);

        // partial: P = S @ Vt^T, tiles 1x8x64 = 512 (fp16 out)
        mma_gemm<false,false,false,true,false><<<gl(512), 256, SMB>>>(
            S, Vt, nullptr, P, nullptr,
            1024, 1024, 1024, 1024,
            16777216, 1048576, 1048576, 65536, 1048576, 64, HH, 1.f, 1, 8, 512);

        // output projection (fp32 out)
        dim3 gwo(32, 32, 1);
        transpose_pk<false,false><<<gwo, blkT>>>(Wo, WoT, nullptr, 1024, 1024, 1024, Z0, Z0, 1);
        mma_gemm<false,false,false,false,false><<<gl(512), 256, SMB>>>(
            P, WoT, nullptr, M, nullptr,
            1024, 1024, 1024, 1024,
            Z0,Z0,Z0,Z0,Z0,Z0, 1, 1.f, 16, 32, 512);

        add_subnorm<<<BB * TT, 256>>>(M, resid_, obuf);
    };

    run_mha(0,        Wq1, Wk1, Wv1, Wo1, y,  o1);
    run_mha((long)XL, Wq2, Wk2, Wv2, Wo2, o1, o2);

    // FFN: hid = relu(y @ W_in^T + b_in), tiles 64x32 = 2048 (fp16 out)
    mma_gemm<true,true,false,true,false><<<gl(2048), 256, SMB>>>(
        xy, Win, b_in, hid, nullptr,
        1024, 1024, 1024, 4096,
        Z0,Z0,Z0,Z0,Z0,Z0, 1, 1.f, 64, 32, 2048);
    // ff = hid @ W_out^T + b_out, tiles 16x32 = 512 (fp32 out)
    mma_gemm<true,false,false,false,false><<<gl(512), 256, SMB>>>(
        hid, Wout, b_out, ff, nullptr,
        4096, 4096, 4096, 1024,
        Z0,Z0,Z0,Z0,Z0,Z0, 1, 1.f, 16, 32, 512);

    add_subnorm<<<BB * TT, 256>>>(ff, o2, out);
}

// round 12
// speedup vs baseline: 3.2347x; 1.0705x over previous
#include <cuda_runtime.h>
#include <cuda_fp16.h>
#include <math.h>
#include <stdint.h>

#define BB 4
#define TT 1024
#define DD 1024
#define HH 16
#define DKV 64
#define FFD 4096

#define XL   (BB * TT * DD)            // 4,194,304
#define WL   (DD * DD)                 // 1,048,576
#define SL   ((long)BB * HH * TT * TT) // 67,108,864
#define HIDL ((long)BB * TT * FFD)     // 16,777,216

// ---- single-plane fp16 format (RN) -------------------------------------------------
__device__ __align__(16) __half g_xy  [2 * XL];       // y, x
__device__ __align__(16) __half g_Wt  [6 * WL];       // q/k/v weights both MHAs (transposed)
__device__ __align__(16) __half g_WoT [2 * WL];
__device__ __align__(16) __half g_Win [4 * WL];
__device__ __align__(16) __half g_Wout[4 * WL];
__device__ __align__(16) __half g_QKV [6 * XL];       // QKV for both MHAs
__device__ __align__(16) __half g_Vt  [2 * XL];
__device__ __align__(16) __half g_S   [2 * SL];       // 268 MB
__device__ __align__(16) __half g_P   [2 * XL];
__device__ __align__(16) __half g_hid [HIDL];
__device__ float g_cpart[2 * BB * HH * 8 * TT];       // column partials, both MHAs (4MB)
__device__ float g_dinv [2 * BB * HH * TT];
__device__ float g_M [2 * XL];
__device__ float g_o1[XL];
__device__ float g_o2[XL];
__device__ float g_ff[XL];

// ---- GEMM segment descriptor --------------------------------------------------------
// flags: 1=BIAS, 2=RELU, 4=EXP, 8=PACK(fp16 out), 16=CSUM
struct GDesc {
    const __half* A; const __half* B;
    const float* bias; void* C; float* cpart;
    int K, lda, ldb, ldc;
    long sA1, sA2, sB1, sB2, sC1, sC2;
    int zdiv; float alpha; int gx, gy;
    int flags; int tile_end;
};

// ---------------- helpers ----------------
__device__ __forceinline__ void mma_f16(float* c, const uint32_t* a, const uint32_t* b) {
    asm volatile(
        "mma.sync.aligned.m16n8k16.row.col.f32.f16.f16.f32 "
        "{%0,%1,%2,%3}, {%4,%5,%6,%7}, {%8,%9}, {%0,%1,%2,%3};"
        : "+f"(c[0]), "+f"(c[1]), "+f"(c[2]), "+f"(c[3])
        : "r"(a[0]), "r"(a[1]), "r"(a[2]), "r"(a[3]), "r"(b[0]), "r"(b[1]));
}

// ---------------- multi-segment fp16 GEMM (persistent) -------------------------------
// Each tile: C[M,N] tile of alpha * A[M,K] @ B[N,K]^T for its segment's descriptor.
// CTA 128x64, 8 warps (4x2), warp tile 32x32, 4-stage cp.async, smem/stage 12 KB.
__global__ __launch_bounds__(256, 3)
void mma_multi(GDesc D0, GDesc D1, GDesc D2, int ntot)
{
    constexpr int NST = 4;
    constexpr int STGH = 6144;           // halves per stage (A 4096 + B 2048)
    constexpr int OFF_B = 4096;

    extern __shared__ __half smh[];
    uint32_t smb;
    asm("{ .reg .u64 t; cvta.to.shared.u64 t, %1; cvt.u32.u64 %0, t; }" : "=r"(smb) : "l"(smh));

    const int tid  = threadIdx.x;
    const int lane = tid & 31;
    const int wid  = tid >> 5;
    const int wm   = wid >> 1;           // 0..3
    const int wn   = wid & 1;            // 0..1
    const int g    = lane >> 2;
    const int tg   = lane & 3;

    const int ar = wm * 32 + g;
    const int br = wn * 32 + g;

    for (int tile = blockIdx.x; tile < ntot; tile += gridDim.x) {
        const bool in0 = tile < D0.tile_end;
        const bool in1 = tile < D1.tile_end;
        const GDesc d = in0 ? D0 : (in1 ? D1 : D2);
        const int base = in0 ? 0 : (in1 ? D0.tile_end : D1.tile_end);

        const int lt  = tile - base;
        const int z   = lt / (d.gx * d.gy);
        const int rem = lt % (d.gx * d.gy);
        const int trow = rem / d.gx;
        const int row0 = trow * 128;
        const int col0 = (rem % d.gx) * 64;
        const int z1 = z / d.zdiv, z2 = z % d.zdiv;
        const __half* Ahz = d.A + z1 * d.sA1 + z2 * d.sA2;
        const __half* Bhz = d.B + z1 * d.sB1 + z2 * d.sB2;
        const long coff = z1 * d.sC1 + z2 * d.sC2;
        const int lda = d.lda, ldb = d.ldb, ldc = d.ldc;
        const int flags = d.flags;

        float acc[2][4][4];
        #pragma unroll
        for (int i = 0; i < 2; i++)
            #pragma unroll
            for (int j = 0; j < 4; j++)
                #pragma unroll
                for (int q = 0; q < 4; q++) acc[i][j][q] = 0.f;

        const int nch = d.K / 32;

        auto copy_stage = [&](int s, int c) {
            const int kk = c * 32;
            #pragma unroll
            for (int i = tid; i < 768; i += 256) {
                const __half* src;
                uint32_t doff;
                if (i < 512) {
                    int r = i >> 2, q = i & 3;
                    src = Ahz + (long)(row0 + r) * lda + kk + q * 8;
                    doff = (uint32_t)(r * 32 + q * 8);
                } else {
                    int j = i - 512;
                    int r = j >> 2, q = j & 3;
                    src = Bhz + (long)(col0 + r) * ldb + kk + q * 8;
                    doff = (uint32_t)(OFF_B + r * 32 + q * 8);
                }
                uint32_t dst = smb + 2u * ((uint32_t)s * STGH + doff);
                asm volatile("cp.async.cg.shared.global [%0], [%1], 16;" :: "r"(dst), "l"(src));
            }
        };

        #pragma unroll
        for (int s = 0; s < NST - 1; s++) {
            if (s < nch) copy_stage(s, s);
            asm volatile("cp.async.commit_group;" ::: "memory");
        }

        for (int c = 0; c < nch; c++) {
            if (c + NST - 1 < nch) copy_stage((c + NST - 1) & (NST - 1), c + NST - 1);
            asm volatile("cp.async.commit_group;" ::: "memory");
            asm volatile("cp.async.wait_group %0;" :: "n"(NST - 1) : "memory");
            __syncthreads();

            const __half* St = smh + (c & (NST - 1)) * STGH;

            uint4 bq[4];
            #pragma unroll
            for (int nt = 0; nt < 4; nt++)
                bq[nt] = *(const uint4*)(St + OFF_B + (br + 8 * nt) * 32 + tg * 8);

            #pragma unroll
            for (int mt = 0; mt < 2; mt++) {
                const __half* arow = St + (ar + 16 * mt) * 32 + tg * 8;
                uint4 h0 = *(const uint4*)(arow);
                uint4 h1 = *(const uint4*)(arow + 8 * 32);
                uint32_t Ah0[4] = {h0.x, h1.x, h0.y, h1.y};
                uint32_t Ah1[4] = {h0.z, h1.z, h0.w, h1.w};
                #pragma unroll
                for (int nt = 0; nt < 4; nt++) {
                    uint32_t b0[2] = {bq[nt].x, bq[nt].y};
                    mma_f16(acc[mt][nt], Ah0, b0);
                }
                #pragma unroll
                for (int nt = 0; nt < 4; nt++) {
                    uint32_t b1[2] = {bq[nt].z, bq[nt].w};
                    mma_f16(acc[mt][nt], Ah1, b1);
                }
            }
            __syncthreads();
        }

        // epilogue
        float* Cf = (float*)d.C;
        __half* Ch = (__half*)d.C;
        const float alpha = d.alpha;
        float cs[4][2];
        #pragma unroll
        for (int nt = 0; nt < 4; nt++) { cs[nt][0] = 0.f; cs[nt][1] = 0.f; }
        const int rbase = row0 + wm * 32 + g;
        const int cbase = col0 + wn * 32 + tg * 2;
        #pragma unroll
        for (int mt = 0; mt < 2; mt++) {
            #pragma unroll
            for (int half_ = 0; half_ < 2; half_++) {
                const long gm = rbase + mt * 16 + half_ * 8;
                const long rowoff = coff + gm * ldc;
                #pragma unroll
                for (int nt = 0; nt < 4; nt++) {
                    const int gn = cbase + nt * 8;
                    float v0 = acc[mt][nt][half_ * 2 + 0] * alpha;
                    float v1 = acc[mt][nt][half_ * 2 + 1] * alpha;
                    if (flags & 4)  { v0 = __expf(v0); v1 = __expf(v1); }
                    if (flags & 1)  { v0 += d.bias[gn]; v1 += d.bias[gn + 1]; }
                    if (flags & 2)  { v0 = fmaxf(v0, 0.f); v1 = fmaxf(v1, 0.f); }
                    if (flags & 16) { cs[nt][0] += v0; cs[nt][1] += v1; }
                    if (flags & 8) {
                        *(__half2*)(Ch + rowoff + gn) =
                            __halves2half2(__float2half_rn(v0), __float2half_rn(v1));
                    } else {
                        float2 o; o.x = v0; o.y = v1;
                        *(float2*)(Cf + rowoff + gn) = o;
                    }
                }
            }
        }

        if (flags & 16) {
            // deterministic per-tile column sums -> cpart[z][trow][col]
            #pragma unroll
            for (int nt = 0; nt < 4; nt++) {
                #pragma unroll
                for (int p = 0; p < 2; p++) {
                    float v = cs[nt][p];
                    v += __shfl_xor_sync(0xffffffffu, v, 4);
                    v += __shfl_xor_sync(0xffffffffu, v, 8);
                    v += __shfl_xor_sync(0xffffffffu, v, 16);
                    cs[nt][p] = v;
                }
            }
            float* colpart = (float*)smh;    // stage buffers dead here
            if (g == 0) {
                #pragma unroll
                for (int nt = 0; nt < 4; nt++) {
                    int lc = wn * 32 + tg * 2 + nt * 8;
                    colpart[wm * 64 + lc]     = cs[nt][0];
                    colpart[wm * 64 + lc + 1] = cs[nt][1];
                }
            }
            __syncthreads();
            if (tid < 64) {
                float s4 = colpart[tid] + colpart[64 + tid] +
                           colpart[128 + tid] + colpart[192 + tid];
                d.cpart[(long)z * 8192 + trow * 1024 + col0 + tid] = s4;
            }
            __syncthreads();
        }
    }
}

// -------- convert pass: fp32 -> fp16 (RN) --------------------------------------------
__global__ void split_pairs(const float* __restrict__ in, __half* __restrict__ out,
                            int npairs) {
    int i = blockIdx.x * 256 + threadIdx.x;
    if (i >= npairs) return;
    float2 v = *(const float2*)(in + 2 * i);
    *(__half2*)(out + 2 * i) = __halves2half2(__float2half_rn(v.x), __float2half_rn(v.y));
}

// -------- dinv from column partials (both MHAs): dinv[i]=1/sum_tr cpart --------------
__global__ void inv_partials(const float* __restrict__ cpart, float* __restrict__ dinv) {
    int i = blockIdx.x * 256 + threadIdx.x;     // 131072 total
    int z = i >> 10, s = i & 1023;
    const float* p = cpart + (long)z * 8192 + s;
    float a = 0.f;
    #pragma unroll
    for (int tr = 0; tr < 8; tr++) a += p[tr * 1024];
    dinv[i] = 1.f / a;
}

// -------- transpose: out[z][c][r] = in[z][r][c] (*scale[z][r]); fp16 out -------------
template<bool SC, bool PIN>
__global__ void transpose_pk(const void* __restrict__ inv, __half* __restrict__ out,
                             const float* __restrict__ scale,
                             int R, int ldin, int ldout,
                             long inS1, long inS2, int zdiv)
{
    __shared__ float tile[32][33];
    const int z = blockIdx.z;
    const long inoff = (long)(z / zdiv) * inS1 + (long)(z % zdiv) * inS2;
    const long outz = (long)z * (long)gridDim.x * 32 * ldout;
    const int c0 = blockIdx.x * 32, r0 = blockIdx.y * 32;
    const int tx = threadIdx.x, ty = threadIdx.y;
    #pragma unroll
    for (int i = ty; i < 32; i += 8) {
        float v;
        long idx = (long)(r0 + i) * ldin + c0 + tx;
        if (PIN) v = __half2float(((const __half*)inv + inoff)[idx]);
        else     v = ((const float*)inv + inoff)[idx];
        if (SC) v *= scale[(long)z * R + r0 + i];
        tile[i][tx] = v;
    }
    __syncthreads();
    #pragma unroll
    for (int i = ty; i < 32; i += 8) {
        long o = outz + (long)(c0 + i) * ldout + r0 + tx;
        out[o] = __float2half_rn(tile[tx][i]);
    }
}

// ---------------- reductions + sub_norm ----------------------------------------------
__device__ __forceinline__ float blockReduceSum(float v) {
    __shared__ float sh[32];
    __syncthreads();
    int lane = threadIdx.x & 31, wid = threadIdx.x >> 5;
    #pragma unroll
    for (int o = 16; o; o >>= 1) v += __shfl_xor_sync(0xffffffffu, v, o);
    if (lane == 0) sh[wid] = v;
    __syncthreads();
    if (wid == 0) {
        v = (threadIdx.x < (blockDim.x >> 5)) ? sh[lane] : 0.f;
        #pragma unroll
        for (int o = 16; o; o >>= 1) v += __shfl_xor_sync(0xffffffffu, v, o);
        if (lane == 0) sh[0] = v;
    }
    __syncthreads();
    return sh[0];
}

__global__ void add_subnorm(const float* __restrict__ A, const float* __restrict__ R,
                            float* __restrict__ O) {
    long base = (long)blockIdx.x * 1024;
    int t = threadIdx.x;
    float v[4];
    float s = 0.f;
    #pragma unroll
    for (int j = 0; j < 4; j++) { v[j] = A[base + t + j * 256] + R[base + t + j * 256]; s += v[j]; }
    s = blockReduceSum(s);
    float mean = s * (1.f / 1024.f);
    float q = 0.f;
    #pragma unroll
    for (int j = 0; j < 4; j++) { float d = v[j] - mean; q += d * d; }
    q = blockReduceSum(q);
    float sd = sqrtf(q * (1.f / 1023.f));
    #pragma unroll
    for (int j = 0; j < 4; j++) O[base + t + j * 256] = v[j] - mean - sd;
}

// ---------------- host -----------------------------------------------------------------
static const int SMB   = 4 * 6144 * 2;    // 49,152 B -> 3 CTAs/SM
static const int PGRID = 456;             // 152 SMs x 3 CTAs

extern "C" void kernel_launch(void* const* d_in, const int* in_sizes, int n_in,
                              void* d_out, int out_size) {
    const float* x    = (const float*)d_in[0];
    const float* y    = (const float*)d_in[1];
    const float* Wq1  = (const float*)d_in[2];
    const float* Wk1  = (const float*)d_in[3];
    const float* Wv1  = (const float*)d_in[4];
    const float* Wo1  = (const float*)d_in[5];
    const float* Wq2  = (const float*)d_in[6];
    const float* Wk2  = (const float*)d_in[7];
    const float* Wv2  = (const float*)d_in[8];
    const float* Wo2  = (const float*)d_in[9];
    const float* W_in = (const float*)d_in[10];
    const float* b_in = (const float*)d_in[11];
    const float* W_out= (const float*)d_in[12];
    const float* b_out= (const float*)d_in[13];
    float* out = (float*)d_out;

    __half *xy, *Wt, *WoT, *Win, *Wout, *QKV, *Vt, *S, *P, *hid;
    float *cpart, *dinv, *M, *o1, *o2, *ff;
    cudaGetSymbolAddress((void**)&xy,  g_xy);
    cudaGetSymbolAddress((void**)&Wt,  g_Wt);
    cudaGetSymbolAddress((void**)&WoT, g_WoT);
    cudaGetSymbolAddress((void**)&Win, g_Win);
    cudaGetSymbolAddress((void**)&Wout,g_Wout);
    cudaGetSymbolAddress((void**)&QKV, g_QKV);
    cudaGetSymbolAddress((void**)&Vt,  g_Vt);
    cudaGetSymbolAddress((void**)&S,   g_S);
    cudaGetSymbolAddress((void**)&P,   g_P);
    cudaGetSymbolAddress((void**)&hid, g_hid);
    cudaGetSymbolAddress((void**)&cpart, g_cpart);
    cudaGetSymbolAddress((void**)&dinv,g_dinv);
    cudaGetSymbolAddress((void**)&M,   g_M);
    cudaGetSymbolAddress((void**)&o1,  g_o1);
    cudaGetSymbolAddress((void**)&o2,  g_o2);
    cudaGetSymbolAddress((void**)&ff,  g_ff);

    cudaFuncSetAttribute(mma_multi, cudaFuncAttributeMaxDynamicSharedMemorySize, SMB);

    dim3 blkT(32, 8);
    auto gl = [&](int nt) { return dim3((unsigned)(nt < PGRID ? nt : PGRID), 1, 1); };

    // ---- upfront converts + weight transposes (all independent)
    split_pairs<<<XL/2/256, 256>>>(y, xy,      XL/2);
    split_pairs<<<XL/2/256, 256>>>(x, xy + XL, XL/2);
    split_pairs<<<4*WL/2/256, 256>>>(W_in,  Win,  4*WL/2);
    split_pairs<<<4*WL/2/256, 256>>>(W_out, Wout, 4*WL/2);
    dim3 gw(2, 32, HH);
    transpose_pk<false,false><<<gw, blkT>>>(Wq1, Wt,          nullptr, 1024, 64, 1024, 65536, 0, 1);
    transpose_pk<false,false><<<gw, blkT>>>(Wk1, Wt + WL,     nullptr, 1024, 64, 1024, 65536, 0, 1);
    transpose_pk<false,false><<<gw, blkT>>>(Wv1, Wt + 2 * WL, nullptr, 1024, 64, 1024, 65536, 0, 1);
    transpose_pk<false,false><<<gw, blkT>>>(Wq2, Wt + 3 * WL, nullptr, 1024, 64, 1024, 65536, 0, 1);
    transpose_pk<false,false><<<gw, blkT>>>(Wk2, Wt + 4 * WL, nullptr, 1024, 64, 1024, 65536, 0, 1);
    transpose_pk<false,false><<<gw, blkT>>>(Wv2, Wt + 5 * WL, nullptr, 1024, 64, 1024, 65536, 0, 1);
    dim3 gwo(32, 32, 1);
    transpose_pk<false,false><<<gwo, blkT>>>(Wo1, WoT,      nullptr, 1024, 1024, 1024, 0, 0, 1);
    transpose_pk<false,false><<<gwo, blkT>>>(Wo2, WoT + WL, nullptr, 1024, 1024, 1024, 0, 0, 1);

    auto mk = [&](const __half* A, const __half* B, const float* bias, void* C,
                  float* cp, int K, int lda, int ldb, int ldc,
                  long a1, long a2, long b1, long b2, long c1, long c2,
                  int zdiv, float alpha, int gx, int gy, int flags, int end) {
        GDesc d;
        d.A = A; d.B = B; d.bias = bias; d.C = C; d.cpart = cp;
        d.K = K; d.lda = lda; d.ldb = ldb; d.ldc = ldc;
        d.sA1 = a1; d.sA2 = a2; d.sB1 = b1; d.sB2 = b2; d.sC1 = c1; d.sC2 = c2;
        d.zdiv = zdiv; d.alpha = alpha; d.gx = gx; d.gy = gy;
        d.flags = flags; d.tile_end = end;
        return d;
    };

    const int PACK = 8, EXP = 4, BIAS = 1, RELU = 2, CSUM = 16;

    // MEGA1: QKV1 (1536) + QKV2 (1536) + FFN1 (2048) = 5120 tiles
    {
        GDesc d0 = mk(xy, Wt, nullptr, QKV, nullptr, 1024, 1024, 1024, 1024,
                      0, 0, 2L*WL, WL, 2L*XL, XL, 2, 1.f, 16, 32, PACK, 1536);
        GDesc d1 = mk(xy, Wt + 3*WL, nullptr, QKV + 3*XL, nullptr, 1024, 1024, 1024, 1024,
                      (long)XL, (long)XL, 2L*WL, WL, 2L*XL, XL, 2, 1.f, 16, 32, PACK, 3072);
        GDesc d2 = mk(xy, Win, b_in, hid, nullptr, 1024, 1024, 1024, 4096,
                      0, 0, 0, 0, 0, 0, 1, 1.f, 64, 32, BIAS|RELU|PACK, 5120);
        mma_multi<<<gl(5120), 256, SMB>>>(d0, d1, d2, 5120);
    }

    // MEGA2: scores1 (8192) + scores2 (8192) + FFN2 (512) = 16896 tiles
    {
        GDesc d0 = mk(QKV, QKV + XL, nullptr, S, cpart, 64, 1024, 1024, 1024,
                      1048576, 64, 1048576, 64, 16777216, 1048576, HH, 0.125f,
                      16, 8, EXP|PACK|CSUM, 8192);
        GDesc d1 = mk(QKV + 3*XL, QKV + 4*XL, nullptr, S + SL, cpart + 524288L,
                      64, 1024, 1024, 1024,
                      1048576, 64, 1048576, 64, 16777216, 1048576, HH, 0.125f,
                      16, 8, EXP|PACK|CSUM, 16384);
        GDesc d2 = mk(hid, Wout, b_out, ff, nullptr, 4096, 4096, 4096, 1024,
                      0, 0, 0, 0, 0, 0, 1, 1.f, 16, 32, BIAS, 16896);
        mma_multi<<<gl(16896), 256, SMB>>>(d0, d1, d2, 16896);
    }

    // dinv for both MHAs (131072 values)
    inv_partials<<<512, 256>>>(cpart, dinv);

    // Vt transposes (both MHAs)
    dim3 gv(2, 32, BB * HH);
    transpose_pk<true,true><<<gv, blkT>>>(QKV + 2*XL, Vt, dinv,
                                          1024, 1024, 1024, 1048576, 64, HH);
    transpose_pk<true,true><<<gv, blkT>>>(QKV + 5*XL, Vt + XL, dinv + 65536,
                                          1024, 1024, 1024, 1048576, 64, HH);

    // MEGA3: P1 (512) + P2 (512) = 1024 tiles
    {
        GDesc d0 = mk(S, Vt, nullptr, P, nullptr, 1024, 1024, 1024, 1024,
                      16777216, 1048576, 1048576, 65536, 1048576, 64, HH, 1.f,
                      1, 8, PACK, 512);
        GDesc d1 = mk(S + SL, Vt + XL, nullptr, P + XL, nullptr, 1024, 1024, 1024, 1024,
                      16777216, 1048576, 1048576, 65536, 1048576, 64, HH, 1.f,
                      1, 8, PACK, 1024);
        mma_multi<<<gl(1024), 256, SMB>>>(d0, d1, d1, 1024);
    }

    // MEGA4: Wo1 (512) + Wo2 (512) = 1024 tiles
    {
        GDesc d0 = mk(P, WoT, nullptr, M, nullptr, 1024, 1024, 1024, 1024,
                      0, 0, 0, 0, 0, 0, 1, 1.f, 16, 32, 0, 512);
        GDesc d1 = mk(P + XL, WoT + WL, nullptr, M + XL, nullptr, 1024, 1024, 1024, 1024,
                      0, 0, 0, 0, 0, 0, 1, 1.f, 16, 32, 0, 1024);
        mma_multi<<<gl(1024), 256, SMB>>>(d0, d1, d1, 1024);
    }

    // residual subnorm chain
    add_subnorm<<<BB * TT, 256>>>(M, y, o1);
    add_subnorm<<<BB * TT, 256>>>(M + XL, o1, o2);
    add_subnorm<<<BB * TT, 256>>>(ff, o2, out);
}

// round 13
// speedup vs baseline: 3.2890x; 1.0168x over previous
#include <cuda_runtime.h>
#include <cuda_fp16.h>
#include <math.h>
#include <stdint.h>

#define BB 4
#define TT 1024
#define DD 1024
#define HH 16
#define DKV 64
#define FFD 4096

#define XL   (BB * TT * DD)            // 4,194,304
#define WL   (DD * DD)                 // 1,048,576
#define SL   ((long)BB * HH * TT * TT) // 67,108,864
#define HIDL ((long)BB * TT * FFD)     // 16,777,216

// ---- single-plane fp16 format (RN) -------------------------------------------------
__device__ __align__(16) __half g_xy  [2 * XL];       // y, x
__device__ __align__(16) __half g_Wt  [6 * WL];       // q/k/v weights both MHAs (transposed)
__device__ __align__(16) __half g_WoT [2 * WL];
__device__ __align__(16) __half g_Win [4 * WL];
__device__ __align__(16) __half g_Wout[4 * WL];
__device__ __align__(16) __half g_QKV [6 * XL];       // QKV for both MHAs
__device__ __align__(16) __half g_Vt  [2 * XL];
__device__ __align__(16) __half g_S   [2 * SL];       // 268 MB
__device__ __align__(16) __half g_P   [2 * XL];
__device__ __align__(16) __half g_hid [HIDL];
__device__ float g_cpart[2 * BB * HH * 8 * TT];       // column partials, both MHAs (4MB)
__device__ float g_dinv [2 * BB * HH * TT];
__device__ float g_M [2 * XL];
__device__ float g_o1[XL];
__device__ float g_o2[XL];
__device__ float g_ff[XL];

// ---- GEMM segment descriptor --------------------------------------------------------
// flags: 1=BIAS, 2=RELU, 4=EXP, 8=PACK(fp16 out), 16=CSUM
struct GDesc {
    const __half* A; const __half* B;
    const float* bias; void* C; float* cpart;
    int K, lda, ldb, ldc;
    long sA1, sA2, sB1, sB2, sC1, sC2;
    int zdiv; float alpha; int gx, gy;
    int flags; int tile_end;
};

// ---------------- helpers ----------------
__device__ __forceinline__ void mma_f16(float* c, const uint32_t* a, const uint32_t* b) {
    asm volatile(
        "mma.sync.aligned.m16n8k16.row.col.f32.f16.f16.f32 "
        "{%0,%1,%2,%3}, {%4,%5,%6,%7}, {%8,%9}, {%0,%1,%2,%3};"
        : "+f"(c[0]), "+f"(c[1]), "+f"(c[2]), "+f"(c[3])
        : "r"(a[0]), "r"(a[1]), "r"(a[2]), "r"(a[3]), "r"(b[0]), "r"(b[1]));
}

// ---------------- multi-segment fp16 GEMM (persistent) -------------------------------
// Each tile: 128x64 of alpha * A[M,K] @ B[N,K]^T for its segment's descriptor.
// 8 warps (4x2), warp tile 32x32, 4-stage cp.async (single sync/chunk).
// PACK epilogue stages the fp16 tile in smem (stride-72 rows, conflict-free) and
// emits coalesced STG.128 rows.
__global__ __launch_bounds__(256, 3)
void mma_multi(GDesc D0, GDesc D1, GDesc D2, int ntot)
{
    constexpr int NST = 4;
    constexpr int STGH = 6144;           // halves per stage (A 4096 + B 2048)
    constexpr int OFF_B = 4096;

    extern __shared__ __half smh[];
    uint32_t smb;
    asm("{ .reg .u64 t; cvta.to.shared.u64 t, %1; cvt.u32.u64 %0, t; }" : "=r"(smb) : "l"(smh));

    const int tid  = threadIdx.x;
    const int lane = tid & 31;
    const int wid  = tid >> 5;
    const int wm   = wid >> 1;           // 0..3
    const int wn   = wid & 1;            // 0..1
    const int g    = lane >> 2;
    const int tg   = lane & 3;

    const int ar = wm * 32 + g;
    const int br = wn * 32 + g;

    for (int tile = blockIdx.x; tile < ntot; tile += gridDim.x) {
        const bool in0 = tile < D0.tile_end;
        const bool in1 = tile < D1.tile_end;
        const GDesc d = in0 ? D0 : (in1 ? D1 : D2);
        const int base = in0 ? 0 : (in1 ? D0.tile_end : D1.tile_end);

        const int lt  = tile - base;
        const int z   = lt / (d.gx * d.gy);
        const int rem = lt % (d.gx * d.gy);
        const int trow = rem / d.gx;
        const int row0 = trow * 128;
        const int col0 = (rem % d.gx) * 64;
        const int z1 = z / d.zdiv, z2 = z % d.zdiv;
        const __half* Ahz = d.A + z1 * d.sA1 + z2 * d.sA2;
        const __half* Bhz = d.B + z1 * d.sB1 + z2 * d.sB2;
        const long coff = z1 * d.sC1 + z2 * d.sC2;
        const int lda = d.lda, ldb = d.ldb, ldc = d.ldc;
        const int flags = d.flags;

        float acc[2][4][4];
        #pragma unroll
        for (int i = 0; i < 2; i++)
            #pragma unroll
            for (int j = 0; j < 4; j++)
                #pragma unroll
                for (int q = 0; q < 4; q++) acc[i][j][q] = 0.f;

        const int nch = d.K / 32;

        auto copy_stage = [&](int s, int c) {
            const int kk = c * 32;
            #pragma unroll
            for (int i = tid; i < 768; i += 256) {
                const __half* src;
                uint32_t doff;
                if (i < 512) {
                    int r = i >> 2, q = i & 3;
                    src = Ahz + (long)(row0 + r) * lda + kk + q * 8;
                    doff = (uint32_t)(r * 32 + q * 8);
                } else {
                    int j = i - 512;
                    int r = j >> 2, q = j & 3;
                    src = Bhz + (long)(col0 + r) * ldb + kk + q * 8;
                    doff = (uint32_t)(OFF_B + r * 32 + q * 8);
                }
                uint32_t dst = smb + 2u * ((uint32_t)s * STGH + doff);
                asm volatile("cp.async.cg.shared.global [%0], [%1], 16;" :: "r"(dst), "l"(src));
            }
        };

        // prologue: stages 0..2
        #pragma unroll
        for (int s = 0; s < NST - 1; s++) {
            if (s < nch) copy_stage(s, s);
            asm volatile("cp.async.commit_group;" ::: "memory");
        }

        for (int c = 0; c < nch; c++) {
            // commits issued so far = 3 + c; wait(2) => commits <= c+1 done => chunk c ready
            asm volatile("cp.async.wait_group %0;" :: "n"(NST - 2) : "memory");
            __syncthreads();   // also licenses overwrite of stage (c+3)&3 == (c-1)&3
            if (c + NST - 1 < nch) copy_stage((c + NST - 1) & (NST - 1), c + NST - 1);
            asm volatile("cp.async.commit_group;" ::: "memory");

            const __half* St = smh + (c & (NST - 1)) * STGH;

            uint4 bq[4];
            #pragma unroll
            for (int nt = 0; nt < 4; nt++)
                bq[nt] = *(const uint4*)(St + OFF_B + (br + 8 * nt) * 32 + tg * 8);

            #pragma unroll
            for (int mt = 0; mt < 2; mt++) {
                const __half* arow = St + (ar + 16 * mt) * 32 + tg * 8;
                uint4 h0 = *(const uint4*)(arow);
                uint4 h1 = *(const uint4*)(arow + 8 * 32);
                uint32_t Ah0[4] = {h0.x, h1.x, h0.y, h1.y};
                uint32_t Ah1[4] = {h0.z, h1.z, h0.w, h1.w};
                #pragma unroll
                for (int nt = 0; nt < 4; nt++) {
                    uint32_t b0[2] = {bq[nt].x, bq[nt].y};
                    mma_f16(acc[mt][nt], Ah0, b0);
                }
                #pragma unroll
                for (int nt = 0; nt < 4; nt++) {
                    uint32_t b1[2] = {bq[nt].z, bq[nt].w};
                    mma_f16(acc[mt][nt], Ah1, b1);
                }
            }
        }

        __syncthreads();   // all compute done; smem stages dead -> reusable as epi buffer

        const float alpha = d.alpha;
        float cs[4][2];
        #pragma unroll
        for (int nt = 0; nt < 4; nt++) { cs[nt][0] = 0.f; cs[nt][1] = 0.f; }

        if (flags & 8) {
            // -------- staged fp16 epilogue: STS (stride-72 rows) -> coalesced STG.128
            __half* eb = smh;                       // 128 x 72 halves = 18 KB
            float* colpart = (float*)(smh + 9216);  // 256 floats
            #pragma unroll
            for (int mt = 0; mt < 2; mt++) {
                #pragma unroll
                for (int half_ = 0; half_ < 2; half_++) {
                    const int er = wm * 32 + mt * 16 + half_ * 8 + g;
                    #pragma unroll
                    for (int nt = 0; nt < 4; nt++) {
                        const int ec = wn * 32 + tg * 2 + nt * 8;
                        float v0 = acc[mt][nt][half_ * 2 + 0] * alpha;
                        float v1 = acc[mt][nt][half_ * 2 + 1] * alpha;
                        if (flags & 4)  { v0 = __expf(v0); v1 = __expf(v1); }
                        if (flags & 1)  { v0 += d.bias[col0 + ec]; v1 += d.bias[col0 + ec + 1]; }
                        if (flags & 2)  { v0 = fmaxf(v0, 0.f); v1 = fmaxf(v1, 0.f); }
                        if (flags & 16) { cs[nt][0] += v0; cs[nt][1] += v1; }
                        *(__half2*)(eb + er * 72 + ec) =
                            __halves2half2(__float2half_rn(v0), __float2half_rn(v1));
                    }
                }
            }
            if (flags & 16) {
                #pragma unroll
                for (int nt = 0; nt < 4; nt++) {
                    #pragma unroll
                    for (int p = 0; p < 2; p++) {
                        float v = cs[nt][p];
                        v += __shfl_xor_sync(0xffffffffu, v, 4);
                        v += __shfl_xor_sync(0xffffffffu, v, 8);
                        v += __shfl_xor_sync(0xffffffffu, v, 16);
                        cs[nt][p] = v;
                    }
                }
                if (g == 0) {
                    #pragma unroll
                    for (int nt = 0; nt < 4; nt++) {
                        int lc = wn * 32 + tg * 2 + nt * 8;
                        colpart[wm * 64 + lc]     = cs[nt][0];
                        colpart[wm * 64 + lc + 1] = cs[nt][1];
                    }
                }
            }
            __syncthreads();
            // coalesced copy: 1024 uint4 (128 rows x 8), 4 per thread
            __half* Ch = (__half*)d.C;
            const long crow0 = coff + (long)row0 * ldc + col0;
            #pragma unroll
            for (int k = 0; k < 4; k++) {
                int j = tid + k * 256;
                int r = j >> 3, u = j & 7;
                uint4 v = *(const uint4*)(eb + r * 72 + u * 8);
                *(uint4*)(Ch + crow0 + (long)r * ldc + u * 8) = v;
            }
            if ((flags & 16) && tid < 64) {
                float s4 = colpart[tid] + colpart[64 + tid] +
                           colpart[128 + tid] + colpart[192 + tid];
                d.cpart[(long)z * 8192 + trow * 1024 + col0 + tid] = s4;
            }
        } else {
            // -------- fp32 direct epilogue (M, ff)
            float* Cf = (float*)d.C;
            const int rbase = row0 + wm * 32 + g;
            const int cbase = col0 + wn * 32 + tg * 2;
            #pragma unroll
            for (int mt = 0; mt < 2; mt++) {
                #pragma unroll
                for (int half_ = 0; half_ < 2; half_++) {
                    const long gm = rbase + mt * 16 + half_ * 8;
                    const long rowoff = coff + gm * ldc;
                    #pragma unroll
                    for (int nt = 0; nt < 4; nt++) {
                        const int gn = cbase + nt * 8;
                        float v0 = acc[mt][nt][half_ * 2 + 0] * alpha;
                        float v1 = acc[mt][nt][half_ * 2 + 1] * alpha;
                        if (flags & 1) { v0 += d.bias[gn]; v1 += d.bias[gn + 1]; }
                        float2 o; o.x = v0; o.y = v1;
                        *(float2*)(Cf + rowoff + gn) = o;
                    }
                }
            }
        }
        __syncthreads();   // epilogue buffer / stages safe before next tile's prologue
    }
}

// -------- convert pass: fp32 -> fp16 (RN) --------------------------------------------
__global__ void split_pairs(const float* __restrict__ in, __half* __restrict__ out,
                            int npairs) {
    int i = blockIdx.x * 256 + threadIdx.x;
    if (i >= npairs) return;
    float2 v = *(const float2*)(in + 2 * i);
    *(__half2*)(out + 2 * i) = __halves2half2(__float2half_rn(v.x), __float2half_rn(v.y));
}

// -------- dinv from column partials (both MHAs) --------------------------------------
__global__ void inv_partials(const float* __restrict__ cpart, float* __restrict__ dinv) {
    int i = blockIdx.x * 256 + threadIdx.x;     // 131072 total
    int z = i >> 10, s = i & 1023;
    const float* p = cpart + (long)z * 8192 + s;
    float a = 0.f;
    #pragma unroll
    for (int tr = 0; tr < 8; tr++) a += p[tr * 1024];
    dinv[i] = 1.f / a;
}

// -------- transpose: out[z][c][r] = in[z][r][c] (*scale[z][r]); fp16 out -------------
template<bool SC, bool PIN>
__global__ void transpose_pk(const void* __restrict__ inv, __half* __restrict__ out,
                             const float* __restrict__ scale,
                             int R, int ldin, int ldout,
                             long inS1, long inS2, int zdiv)
{
    __shared__ float tile[32][33];
    const int z = blockIdx.z;
    const long inoff = (long)(z / zdiv) * inS1 + (long)(z % zdiv) * inS2;
    const long outz = (long)z * (long)gridDim.x * 32 * ldout;
    const int c0 = blockIdx.x * 32, r0 = blockIdx.y * 32;
    const int tx = threadIdx.x, ty = threadIdx.y;
    #pragma unroll
    for (int i = ty; i < 32; i += 8) {
        float v;
        long idx = (long)(r0 + i) * ldin + c0 + tx;
        if (PIN) v = __half2float(((const __half*)inv + inoff)[idx]);
        else     v = ((const float*)inv + inoff)[idx];
        if (SC) v *= scale[(long)z * R + r0 + i];
        tile[i][tx] = v;
    }
    __syncthreads();
    #pragma unroll
    for (int i = ty; i < 32; i += 8) {
        long o = outz + (long)(c0 + i) * ldout + r0 + tx;
        out[o] = __float2half_rn(tile[tx][i]);
    }
}

// ---------------- reductions + sub_norm ----------------------------------------------
__device__ __forceinline__ float blockReduceSum(float v) {
    __shared__ float sh[32];
    __syncthreads();
    int lane = threadIdx.x & 31, wid = threadIdx.x >> 5;
    #pragma unroll
    for (int o = 16; o; o >>= 1) v += __shfl_xor_sync(0xffffffffu, v, o);
    if (lane == 0) sh[wid] = v;
    __syncthreads();
    if (wid == 0) {
        v = (threadIdx.x < (blockDim.x >> 5)) ? sh[lane] : 0.f;
        #pragma unroll
        for (int o = 16; o; o >>= 1) v += __shfl_xor_sync(0xffffffffu, v, o);
        if (lane == 0) sh[0] = v;
    }
    __syncthreads();
    return sh[0];
}

__global__ void add_subnorm(const float* __restrict__ A, const float* __restrict__ R,
                            float* __restrict__ O) {
    long base = (long)blockIdx.x * 1024;
    int t = threadIdx.x;
    float v[4];
    float s = 0.f;
    #pragma unroll
    for (int j = 0; j < 4; j++) { v[j] = A[base + t + j * 256] + R[base + t + j * 256]; s += v[j]; }
    s = blockReduceSum(s);
    float mean = s * (1.f / 1024.f);
    float q = 0.f;
    #pragma unroll
    for (int j = 0; j < 4; j++) { float d = v[j] - mean; q += d * d; }
    q = blockReduceSum(q);
    float sd = sqrtf(q * (1.f / 1023.f));
    #pragma unroll
    for (int j = 0; j < 4; j++) O[base + t + j * 256] = v[j] - mean - sd;
}

// ---------------- host -----------------------------------------------------------------
static const int SMB   = 4 * 6144 * 2;    // 49,152 B -> 3 CTAs/SM
static const int PGRID = 456;             // 152 SMs x 3 CTAs

extern "C" void kernel_launch(void* const* d_in, const int* in_sizes, int n_in,
                              void* d_out, int out_size) {
    const float* x    = (const float*)d_in[0];
    const float* y    = (const float*)d_in[1];
    const float* Wq1  = (const float*)d_in[2];
    const float* Wk1  = (const float*)d_in[3];
    const float* Wv1  = (const float*)d_in[4];
    const float* Wo1  = (const float*)d_in[5];
    const float* Wq2  = (const float*)d_in[6];
    const float* Wk2  = (const float*)d_in[7];
    const float* Wv2  = (const float*)d_in[8];
    const float* Wo2  = (const float*)d_in[9];
    const float* W_in = (const float*)d_in[10];
    const float* b_in = (const float*)d_in[11];
    const float* W_out= (const float*)d_in[12];
    const float* b_out= (const float*)d_in[13];
    float* out = (float*)d_out;

    __half *xy, *Wt, *WoT, *Win, *Wout, *QKV, *Vt, *S, *P, *hid;
    float *cpart, *dinv, *M, *o1, *o2, *ff;
    cudaGetSymbolAddress((void**)&xy,  g_xy);
    cudaGetSymbolAddress((void**)&Wt,  g_Wt);
    cudaGetSymbolAddress((void**)&WoT, g_WoT);
    cudaGetSymbolAddress((void**)&Win, g_Win);
    cudaGetSymbolAddress((void**)&Wout,g_Wout);
    cudaGetSymbolAddress((void**)&QKV, g_QKV);
    cudaGetSymbolAddress((void**)&Vt,  g_Vt);
    cudaGetSymbolAddress((void**)&S,   g_S);
    cudaGetSymbolAddress((void**)&P,   g_P);
    cudaGetSymbolAddress((void**)&hid, g_hid);
    cudaGetSymbolAddress((void**)&cpart, g_cpart);
    cudaGetSymbolAddress((void**)&dinv,g_dinv);
    cudaGetSymbolAddress((void**)&M,   g_M);
    cudaGetSymbolAddress((void**)&o1,  g_o1);
    cudaGetSymbolAddress((void**)&o2,  g_o2);
    cudaGetSymbolAddress((void**)&ff,  g_ff);

    cudaFuncSetAttribute(mma_multi, cudaFuncAttributeMaxDynamicSharedMemorySize, SMB);

    dim3 blkT(32, 8);
    auto gl = [&](int nt) { return dim3((unsigned)(nt < PGRID ? nt : PGRID), 1, 1); };

    // ---- upfront converts + weight transposes (all independent)
    split_pairs<<<XL/2/256, 256>>>(y, xy,      XL/2);
    split_pairs<<<XL/2/256, 256>>>(x, xy + XL, XL/2);
    split_pairs<<<4*WL/2/256, 256>>>(W_in,  Win,  4*WL/2);
    split_pairs<<<4*WL/2/256, 256>>>(W_out, Wout, 4*WL/2);
    dim3 gw(2, 32, HH);
    transpose_pk<false,false><<<gw, blkT>>>(Wq1, Wt,          nullptr, 1024, 64, 1024, 65536, 0, 1);
    transpose_pk<false,false><<<gw, blkT>>>(Wk1, Wt + WL,     nullptr, 1024, 64, 1024, 65536, 0, 1);
    transpose_pk<false,false><<<gw, blkT>>>(Wv1, Wt + 2 * WL, nullptr, 1024, 64, 1024, 65536, 0, 1);
    transpose_pk<false,false><<<gw, blkT>>>(Wq2, Wt + 3 * WL, nullptr, 1024, 64, 1024, 65536, 0, 1);
    transpose_pk<false,false><<<gw, blkT>>>(Wk2, Wt + 4 * WL, nullptr, 1024, 64, 1024, 65536, 0, 1);
    transpose_pk<false,false><<<gw, blkT>>>(Wv2, Wt + 5 * WL, nullptr, 1024, 64, 1024, 65536, 0, 1);
    dim3 gwo(32, 32, 1);
    transpose_pk<false,false><<<gwo, blkT>>>(Wo1, WoT,      nullptr, 1024, 1024, 1024, 0, 0, 1);
    transpose_pk<false,false><<<gwo, blkT>>>(Wo2, WoT + WL, nullptr, 1024, 1024, 1024, 0, 0, 1);

    auto mk = [&](const __half* A, const __half* B, const float* bias, void* C,
                  float* cp, int K, int lda, int ldb, int ldc,
                  long a1, long a2, long b1, long b2, long c1, long c2,
                  int zdiv, float alpha, int gx, int gy, int flags, int end) {
        GDesc d;
        d.A = A; d.B = B; d.bias = bias; d.C = C; d.cpart = cp;
        d.K = K; d.lda = lda; d.ldb = ldb; d.ldc = ldc;
        d.sA1 = a1; d.sA2 = a2; d.sB1 = b1; d.sB2 = b2; d.sC1 = c1; d.sC2 = c2;
        d.zdiv = zdiv; d.alpha = alpha; d.gx = gx; d.gy = gy;
        d.flags = flags; d.tile_end = end;
        return d;
    };

    const int PACK = 8, EXP = 4, BIAS = 1, RELU = 2, CSUM = 16;

    // MEGA1: QKV1 (1536) + QKV2 (1536) + FFN1 (2048) = 5120 tiles
    {
        GDesc d0 = mk(xy, Wt, nullptr, QKV, nullptr, 1024, 1024, 1024, 1024,
                      0, 0, 2L*WL, WL, 2L*XL, XL, 2, 1.f, 16, 32, PACK, 1536);
        GDesc d1 = mk(xy, Wt + 3*WL, nullptr, QKV + 3*XL, nullptr, 1024, 1024, 1024, 1024,
                      (long)XL, (long)XL, 2L*WL, WL, 2L*XL, XL, 2, 1.f, 16, 32, PACK, 3072);
        GDesc d2 = mk(xy, Win, b_in, hid, nullptr, 1024, 1024, 1024, 4096,
                      0, 0, 0, 0, 0, 0, 1, 1.f, 64, 32, BIAS|RELU|PACK, 5120);
        mma_multi<<<gl(5120), 256, SMB>>>(d0, d1, d2, 5120);
    }

    // MEGA2: scores1 (8192) + scores2 (8192) + FFN2 (512) = 16896 tiles
    {
        GDesc d0 = mk(QKV, QKV + XL, nullptr, S, cpart, 64, 1024, 1024, 1024,
                      1048576, 64, 1048576, 64, 16777216, 1048576, HH, 0.125f,
                      16, 8, EXP|PACK|CSUM, 8192);
        GDesc d1 = mk(QKV + 3*XL, QKV + 4*XL, nullptr, S + SL, cpart + 524288L,
                      64, 1024, 1024, 1024,
                      1048576, 64, 1048576, 64, 16777216, 1048576, HH, 0.125f,
                      16, 8, EXP|PACK|CSUM, 16384);
        GDesc d2 = mk(hid, Wout, b_out, ff, nullptr, 4096, 4096, 4096, 1024,
                      0, 0, 0, 0, 0, 0, 1, 1.f, 16, 32, BIAS, 16896);
        mma_multi<<<gl(16896), 256, SMB>>>(d0, d1, d2, 16896);
    }

    // dinv for both MHAs (131072 values)
    inv_partials<<<512, 256>>>(cpart, dinv);

    // Vt transposes (both MHAs)
    dim3 gv(2, 32, BB * HH);
    transpose_pk<true,true><<<gv, blkT>>>(QKV + 2*XL, Vt, dinv,
                                          1024, 1024, 1024, 1048576, 64, HH);
    transpose_pk<true,true><<<gv, blkT>>>(QKV + 5*XL, Vt + XL, dinv + 65536,
                                          1024, 1024, 1024, 1048576, 64, HH);

    // MEGA3: P1 (512) + P2 (512) = 1024 tiles
    {
        GDesc d0 = mk(S, Vt, nullptr, P, nullptr, 1024, 1024, 1024, 1024,
                      16777216, 1048576, 1048576, 65536, 1048576, 64, HH, 1.f,
                      1, 8, PACK, 512);
        GDesc d1 = mk(S + SL, Vt + XL, nullptr, P + XL, nullptr, 1024, 1024, 1024, 1024,
                      16777216, 1048576, 1048576, 65536, 1048576, 64, HH, 1.f,
                      1, 8, PACK, 1024);
        mma_multi<<<gl(1024), 256, SMB>>>(d0, d1, d1, 1024);
    }

    // MEGA4: Wo1 (512) + Wo2 (512) = 1024 tiles
    {
        GDesc d0 = mk(P, WoT, nullptr, M, nullptr, 1024, 1024, 1024, 1024,
                      0, 0, 0, 0, 0, 0, 1, 1.f, 16, 32, 0, 512);
        GDesc d1 = mk(P + XL, WoT + WL, nullptr, M + XL, nullptr, 1024, 1024, 1024, 1024,
                      0, 0, 0, 0, 0, 0, 1, 1.f, 16, 32, 0, 1024);
        mma_multi<<<gl(1024), 256, SMB>>>(d0, d1, d1, 1024);
    }

    // residual subnorm chain
    add_subnorm<<<BB * TT, 256>>>(M, y, o1);
    add_subnorm<<<BB * TT, 256>>>(M + XL, o1, o2);
    add_subnorm<<<BB * TT, 256>>>(ff, o2, out);
}